// round 1
// baseline (speedup 1.0000x reference)
#include <cuda_runtime.h>
#include <cstdint>

#define B_SZ  2
#define HEADS 16
#define TKN   2048
#define DM    1024
#define DK    64

// Scratch (allocation-free rule: __device__ globals)
__device__ float g_Qh[B_SZ * HEADS * TKN * DK];
__device__ float g_Kh[B_SZ * HEADS * TKN * DK];
__device__ float g_Vh[B_SZ * HEADS * TKN * DK];
__device__ float g_ctx[B_SZ * HEADS * TKN * DK];

// ---------------------------------------------------------------------------
// Kernel 1: fused per-head Q/K/V projections.
// Out[b,h,t,k] = sum_d X[b,t,d] * W[h,d,k] + bias[h,k]
// Per (b,h): GEMM M=2048(T tiles of 64), N=64, K=1024 (BK=16).
// grid = (T/64, B*H, 3), block = 256, 4x4 micro-tile per thread.
// ---------------------------------------------------------------------------
__global__ __launch_bounds__(256) void proj_kernel(
    const float* __restrict__ Q, const float* __restrict__ K, const float* __restrict__ V,
    const float* __restrict__ Wq, const float* __restrict__ bq,
    const float* __restrict__ Wk, const float* __restrict__ bk,
    const float* __restrict__ Wv, const float* __restrict__ bv)
{
    __shared__ float At[16][68];   // transposed X tile: At[d][t]
    __shared__ float Bs[16][68];   // W tile: Bs[d][k]

    const float* X; const float* W; const float* bias; float* out;
    int z = blockIdx.z;
    if (z == 0)      { X = Q; W = Wq; bias = bq; out = g_Qh; }
    else if (z == 1) { X = K; W = Wk; bias = bk; out = g_Kh; }
    else             { X = V; W = Wv; bias = bv; out = g_Vh; }

    int bh = blockIdx.y;
    int b = bh >> 4, h = bh & 15;
    int t0 = blockIdx.x * 64;

    const float* Xb = X + ((size_t)b * TKN + t0) * DM;
    const float* Wh = W + (size_t)h * DM * DK;

    int tid = threadIdx.x;
    int ty = tid >> 4, tx = tid & 15;
    int ar = tid >> 2, ac = tid & 3;    // A loader: 64 rows x 4 float4-groups
    int br = tid >> 4, bc = tid & 15;   // B loader: 16 rows x 16 float4-groups

    float acc[4][4] = {};

    for (int d0 = 0; d0 < DM; d0 += 16) {
        float4 a4 = *(const float4*)(Xb + (size_t)ar * DM + d0 + ac * 4);
        float4 b4 = *(const float4*)(Wh + (size_t)(d0 + br) * DK + bc * 4);
        At[ac * 4 + 0][ar] = a4.x;
        At[ac * 4 + 1][ar] = a4.y;
        At[ac * 4 + 2][ar] = a4.z;
        At[ac * 4 + 3][ar] = a4.w;
        *(float4*)&Bs[br][bc * 4] = b4;
        __syncthreads();
#pragma unroll
        for (int kk = 0; kk < 16; kk++) {
            float4 av  = *(const float4*)&At[kk][ty * 4];
            float4 bv4 = *(const float4*)&Bs[kk][tx * 4];
            float aa[4] = {av.x, av.y, av.z, av.w};
            float bb[4] = {bv4.x, bv4.y, bv4.z, bv4.w};
#pragma unroll
            for (int i = 0; i < 4; i++)
#pragma unroll
                for (int j = 0; j < 4; j++)
                    acc[i][j] = fmaf(aa[i], bb[j], acc[i][j]);
        }
        __syncthreads();
    }

    float4 bias4 = *(const float4*)(bias + h * DK + tx * 4);
    float bb[4] = {bias4.x, bias4.y, bias4.z, bias4.w};
    float* outp = out + ((size_t)bh * TKN + t0) * DK;
#pragma unroll
    for (int i = 0; i < 4; i++) {
        float4 o;
        o.x = acc[i][0] + bb[0];
        o.y = acc[i][1] + bb[1];
        o.z = acc[i][2] + bb[2];
        o.w = acc[i][3] + bb[3];
        *(float4*)(outp + (size_t)(ty * 4 + i) * DK + tx * 4) = o;
    }
}

// ---------------------------------------------------------------------------
// Kernel 2: flash attention per (b,h, 64-query tile).
// Online softmax over 2048 keys in tiles of 64. Scale folded into Q.
// ---------------------------------------------------------------------------
__global__ __launch_bounds__(256) void flash_kernel()
{
    extern __shared__ float sm[];
    float* Qt = sm;                  // [64][68] transposed: Qt[k*68 + row]
    float* Kt = sm + 64 * 68;        // [64][68] transposed: Kt[k*68 + key]; reused as P[row*68 + key]
    float* Vs = sm + 2 * 64 * 68;    // [64][68] natural: Vs[s*68 + d]

    int bh = blockIdx.y;
    int t0 = blockIdx.x * 64;
    const float* Qp = g_Qh + (size_t)bh * TKN * DK;
    const float* Kp = g_Kh + (size_t)bh * TKN * DK;
    const float* Vp = g_Vh + (size_t)bh * TKN * DK;

    int tid = threadIdx.x;
    int ty = tid >> 4, tx = tid & 15;
    int lrow = tid >> 4;   // loader row base 0..15
    int kg = tid & 15;     // loader float4 group 0..15

    // Load Q tile transposed, pre-scaled by 1/sqrt(64)
#pragma unroll
    for (int m = 0; m < 4; m++) {
        int row = lrow + m * 16;
        float4 v = *(const float4*)(Qp + (size_t)(t0 + row) * DK + kg * 4);
        Qt[(kg * 4 + 0) * 68 + row] = v.x * 0.125f;
        Qt[(kg * 4 + 1) * 68 + row] = v.y * 0.125f;
        Qt[(kg * 4 + 2) * 68 + row] = v.z * 0.125f;
        Qt[(kg * 4 + 3) * 68 + row] = v.w * 0.125f;
    }

    float m_i[4], l_i[4], O[4][4];
#pragma unroll
    for (int i = 0; i < 4; i++) {
        m_i[i] = -1e30f;
        l_i[i] = 0.0f;
#pragma unroll
        for (int j = 0; j < 4; j++) O[i][j] = 0.0f;
    }

    for (int s0 = 0; s0 < TKN; s0 += 64) {
        __syncthreads();   // previous P/V fully consumed
#pragma unroll
        for (int m = 0; m < 4; m++) {
            int row = lrow + m * 16;
            float4 kv = *(const float4*)(Kp + (size_t)(s0 + row) * DK + kg * 4);
            Kt[(kg * 4 + 0) * 68 + row] = kv.x;
            Kt[(kg * 4 + 1) * 68 + row] = kv.y;
            Kt[(kg * 4 + 2) * 68 + row] = kv.z;
            Kt[(kg * 4 + 3) * 68 + row] = kv.w;
            float4 vv = *(const float4*)(Vp + (size_t)(s0 + row) * DK + kg * 4);
            *(float4*)&Vs[row * 68 + kg * 4] = vv;
        }
        __syncthreads();

        // S = Q K^T  (64x64 tile, 4x4 per thread)
        float S[4][4] = {};
#pragma unroll 8
        for (int kk = 0; kk < 64; kk++) {
            float4 av = *(const float4*)&Qt[kk * 68 + ty * 4];
            float4 bv = *(const float4*)&Kt[kk * 68 + tx * 4];
            float aa[4] = {av.x, av.y, av.z, av.w};
            float bb[4] = {bv.x, bv.y, bv.z, bv.w};
#pragma unroll
            for (int i = 0; i < 4; i++)
#pragma unroll
                for (int j = 0; j < 4; j++)
                    S[i][j] = fmaf(aa[i], bb[j], S[i][j]);
        }

        // online softmax update (rows spread over the 16 tx lanes of each half-warp)
#pragma unroll
        for (int i = 0; i < 4; i++) {
            float mt = fmaxf(fmaxf(S[i][0], S[i][1]), fmaxf(S[i][2], S[i][3]));
            mt = fmaxf(mt, __shfl_xor_sync(0xffffffffu, mt, 1));
            mt = fmaxf(mt, __shfl_xor_sync(0xffffffffu, mt, 2));
            mt = fmaxf(mt, __shfl_xor_sync(0xffffffffu, mt, 4));
            mt = fmaxf(mt, __shfl_xor_sync(0xffffffffu, mt, 8));
            float mnew = fmaxf(m_i[i], mt);
            float corr = __expf(m_i[i] - mnew);
            float rs = 0.0f;
#pragma unroll
            for (int j = 0; j < 4; j++) {
                S[i][j] = __expf(S[i][j] - mnew);
                rs += S[i][j];
            }
            rs += __shfl_xor_sync(0xffffffffu, rs, 1);
            rs += __shfl_xor_sync(0xffffffffu, rs, 2);
            rs += __shfl_xor_sync(0xffffffffu, rs, 4);
            rs += __shfl_xor_sync(0xffffffffu, rs, 8);
            l_i[i] = l_i[i] * corr + rs;
            m_i[i] = mnew;
#pragma unroll
            for (int j = 0; j < 4; j++) O[i][j] *= corr;
        }

        __syncthreads();   // everyone done reading Kt
        // write P into Kt's storage, natural layout P[row][key]
#pragma unroll
        for (int i = 0; i < 4; i++) {
            float4 p4 = make_float4(S[i][0], S[i][1], S[i][2], S[i][3]);
            *(float4*)&Kt[(ty * 4 + i) * 68 + tx * 4] = p4;
        }
        __syncthreads();

        // O += P @ V
#pragma unroll 8
        for (int s = 0; s < 64; s++) {
            float4 vv = *(const float4*)&Vs[s * 68 + tx * 4];
            float vb[4] = {vv.x, vv.y, vv.z, vv.w};
#pragma unroll
            for (int i = 0; i < 4; i++) {
                float pr = Kt[(ty * 4 + i) * 68 + s];
#pragma unroll
                for (int j = 0; j < 4; j++)
                    O[i][j] = fmaf(pr, vb[j], O[i][j]);
            }
        }
    }

    float* cp = g_ctx + (size_t)bh * TKN * DK;
#pragma unroll
    for (int i = 0; i < 4; i++) {
        float inv = 1.0f / l_i[i];
        float4 o = make_float4(O[i][0] * inv, O[i][1] * inv, O[i][2] * inv, O[i][3] * inv);
        *(float4*)(cp + (size_t)(t0 + ty * 4 + i) * DK + tx * 4) = o;
    }
}

// ---------------------------------------------------------------------------
// Kernel 3: output projection.
// The reference's head-scrambling .view of [B,H,T,dk] into [B,T,H*dk] is a
// plain flat reinterpretation of the contiguous ctx buffer, so read it as
// X[4096][1024]. out[n,j] = sum_d X[n,d] * Wo[j,d] + bo[j].
// grid = (DM/64, 4096/64), block = 256, 4x4 micro-tile.
// ---------------------------------------------------------------------------
__global__ __launch_bounds__(256) void outproj_kernel(
    const float* __restrict__ Wo, const float* __restrict__ bo, float* __restrict__ out)
{
    __shared__ float At[16][68];   // transposed X tile: At[d][n]
    __shared__ float Bt[16][68];   // transposed Wo tile: Bt[d][j]

    int j0 = blockIdx.x * 64;
    int m0 = blockIdx.y * 64;
    int tid = threadIdx.x;
    int ty = tid >> 4, tx = tid & 15;
    int ar = tid >> 2, ac = tid & 3;

    const float* X = g_ctx;   // flat [4096][1024]
    float acc[4][4] = {};

    for (int d0 = 0; d0 < DM; d0 += 16) {
        float4 a4 = *(const float4*)(X  + (size_t)(m0 + ar) * DM + d0 + ac * 4);
        float4 w4 = *(const float4*)(Wo + (size_t)(j0 + ar) * DM + d0 + ac * 4);
        At[ac * 4 + 0][ar] = a4.x;
        At[ac * 4 + 1][ar] = a4.y;
        At[ac * 4 + 2][ar] = a4.z;
        At[ac * 4 + 3][ar] = a4.w;
        Bt[ac * 4 + 0][ar] = w4.x;
        Bt[ac * 4 + 1][ar] = w4.y;
        Bt[ac * 4 + 2][ar] = w4.z;
        Bt[ac * 4 + 3][ar] = w4.w;
        __syncthreads();
#pragma unroll
        for (int kk = 0; kk < 16; kk++) {
            float4 av = *(const float4*)&At[kk][ty * 4];
            float4 bv = *(const float4*)&Bt[kk][tx * 4];
            float aa[4] = {av.x, av.y, av.z, av.w};
            float bb[4] = {bv.x, bv.y, bv.z, bv.w};
#pragma unroll
            for (int i = 0; i < 4; i++)
#pragma unroll
                for (int j = 0; j < 4; j++)
                    acc[i][j] = fmaf(aa[i], bb[j], acc[i][j]);
        }
        __syncthreads();
    }

    float4 bias4 = *(const float4*)(bo + j0 + tx * 4);
    float bb[4] = {bias4.x, bias4.y, bias4.z, bias4.w};
#pragma unroll
    for (int i = 0; i < 4; i++) {
        float4 o;
        o.x = acc[i][0] + bb[0];
        o.y = acc[i][1] + bb[1];
        o.z = acc[i][2] + bb[2];
        o.w = acc[i][3] + bb[3];
        *(float4*)(out + (size_t)(m0 + ty * 4 + i) * DM + j0 + tx * 4) = o;
    }
}

// ---------------------------------------------------------------------------
extern "C" void kernel_launch(void* const* d_in, const int* in_sizes, int n_in,
                              void* d_out, int out_size)
{
    const float* Q  = (const float*)d_in[0];
    const float* K  = (const float*)d_in[1];
    const float* V  = (const float*)d_in[2];
    const float* Wq = (const float*)d_in[3];
    const float* bq = (const float*)d_in[4];
    const float* Wk = (const float*)d_in[5];
    const float* bk = (const float*)d_in[6];
    const float* Wv = (const float*)d_in[7];
    const float* bv = (const float*)d_in[8];
    const float* Wo = (const float*)d_in[9];
    const float* bo = (const float*)d_in[10];
    float* out = (float*)d_out;

    // 3 * 64 * 68 * 4 bytes = 52224 (> 48KB default) — idempotent, capture-safe.
    cudaFuncSetAttribute(flash_kernel, cudaFuncAttributeMaxDynamicSharedMemorySize, 52224);

    dim3 g1(TKN / 64, B_SZ * HEADS, 3);
    proj_kernel<<<g1, 256>>>(Q, K, V, Wq, bq, Wk, bk, Wv, bv);

    dim3 g2(TKN / 64, B_SZ * HEADS);
    flash_kernel<<<g2, 256, 52224>>>();

    dim3 g3(DM / 64, (B_SZ * TKN) / 64);
    outproj_kernel<<<g3, 256>>>(Wo, bo, out);
}

// round 2
// speedup vs baseline: 1.0500x; 1.0500x over previous
#include <cuda_runtime.h>
#include <cstdint>

#define B_SZ  2
#define HEADS 16
#define TKN   2048
#define DM    1024
#define DK    64

typedef unsigned long long u64t;

// ---- packed f32x2 helpers (SASS FFMA2 — PTX-only, ptxas never auto-fuses) ----
__device__ __forceinline__ u64t pack2(float lo, float hi) {
    u64t r; asm("mov.b64 %0, {%1,%2};" : "=l"(r) : "f"(lo), "f"(hi)); return r;
}
__device__ __forceinline__ void fma2(u64t& d, u64t a, u64t b) {
    asm("fma.rn.f32x2 %0, %1, %2, %0;" : "+l"(d) : "l"(a), "l"(b));
}
__device__ __forceinline__ void mul2(u64t& d, u64t a) {
    asm("mul.rn.f32x2 %0, %0, %1;" : "+l"(d) : "l"(a));
}
__device__ __forceinline__ float2 unpack2(u64t v) {
    float2 r; asm("mov.b64 {%0,%1}, %2;" : "=f"(r.x), "=f"(r.y) : "l"(v)); return r;
}

// Scratch (allocation-free rule: __device__ globals)
__device__ float g_Qh[B_SZ * HEADS * TKN * DK];
__device__ float g_Kh[B_SZ * HEADS * TKN * DK];
__device__ float g_Vh[B_SZ * HEADS * TKN * DK];
__device__ float g_ctx[B_SZ * HEADS * TKN * DK];

// ---------------------------------------------------------------------------
// Kernel 1: fused per-head Q/K/V projections, 2 heads per block.
// Tile: M=128 (T rows), N=128 (2 heads x DK), BK=16. 256 thr, 8x8/thread.
// grid = (T/128, B*H/2, 3)
// ---------------------------------------------------------------------------
__global__ __launch_bounds__(256) void proj_kernel(
    const float* __restrict__ Q, const float* __restrict__ K, const float* __restrict__ V,
    const float* __restrict__ Wq, const float* __restrict__ bq,
    const float* __restrict__ Wk, const float* __restrict__ bk,
    const float* __restrict__ Wv, const float* __restrict__ bv)
{
    __shared__ float At[16][132];   // transposed X tile: At[d][t]
    __shared__ float Bs[16][132];   // W tile (2 heads): Bs[d][c], c = head_local*64 + k

    const float* X; const float* W; const float* bias; float* out;
    int z = blockIdx.z;
    if (z == 0)      { X = Q; W = Wq; bias = bq; out = g_Qh; }
    else if (z == 1) { X = K; W = Wk; bias = bk; out = g_Kh; }
    else             { X = V; W = Wv; bias = bv; out = g_Vh; }

    int y = blockIdx.y;            // 0..15
    int b = y >> 3, hq = y & 7;
    int h0 = hq * 2;
    int t0 = blockIdx.x * 128;

    const float* Xb = X + ((size_t)b * TKN + t0) * DM;
    const float* W0 = W + (size_t)h0 * DM * DK;
    const float* W1 = W0 + (size_t)DM * DK;

    int tid = threadIdx.x;
    int ty = tid >> 4, tx = tid & 15;
    int ar = tid >> 2, ac = tid & 3;     // A loader: 64 rows (x2) x 4 float4 groups
    int br = tid >> 4, bc = tid & 15;    // B loader: 16 rows x 16 float4 groups

    u64t acc[4][8];
#pragma unroll
    for (int i = 0; i < 4; i++)
#pragma unroll
        for (int j = 0; j < 8; j++) acc[i][j] = 0ULL;

    for (int d0 = 0; d0 < DM; d0 += 16) {
        float4 a4  = *(const float4*)(Xb + (size_t)ar * DM + d0 + ac * 4);
        float4 a4b = *(const float4*)(Xb + (size_t)(ar + 64) * DM + d0 + ac * 4);
        float4 w0  = *(const float4*)(W0 + (size_t)(d0 + br) * DK + bc * 4);
        float4 w1  = *(const float4*)(W1 + (size_t)(d0 + br) * DK + bc * 4);
        At[ac * 4 + 0][ar] = a4.x;  At[ac * 4 + 0][ar + 64] = a4b.x;
        At[ac * 4 + 1][ar] = a4.y;  At[ac * 4 + 1][ar + 64] = a4b.y;
        At[ac * 4 + 2][ar] = a4.z;  At[ac * 4 + 2][ar + 64] = a4b.z;
        At[ac * 4 + 3][ar] = a4.w;  At[ac * 4 + 3][ar + 64] = a4b.w;
        *(float4*)&Bs[br][bc * 4]      = w0;
        *(float4*)&Bs[br][64 + bc * 4] = w1;
        __syncthreads();
#pragma unroll
        for (int kk = 0; kk < 16; kk++) {
            float4 a0 = *(const float4*)&At[kk][ty * 8];
            float4 a1 = *(const float4*)&At[kk][ty * 8 + 4];
            float4 b0 = *(const float4*)&Bs[kk][tx * 8];
            float4 b1 = *(const float4*)&Bs[kk][tx * 8 + 4];
            u64t ap[4] = { pack2(a0.x, a0.y), pack2(a0.z, a0.w),
                           pack2(a1.x, a1.y), pack2(a1.z, a1.w) };
            float bf[8] = { b0.x, b0.y, b0.z, b0.w, b1.x, b1.y, b1.z, b1.w };
#pragma unroll
            for (int j = 0; j < 8; j++) {
                u64t bp = pack2(bf[j], bf[j]);
#pragma unroll
                for (int i = 0; i < 4; i++) fma2(acc[i][j], ap[i], bp);
            }
        }
        __syncthreads();
    }

    // epilogue: thread cols = tx*8 .. tx*8+7 (all within one head)
    int hh = tx >> 3;                 // 0/1 within block
    int kc = (tx & 7) * 8;            // local col within head
    const float* bptr = bias + (h0 + hh) * DK + kc;
    float bb[8];
#pragma unroll
    for (int j = 0; j < 8; j++) bb[j] = bptr[j];

    float* outp = out + (((size_t)(b * HEADS + h0 + hh) * TKN + t0) * DK) + kc;
#pragma unroll
    for (int i2 = 0; i2 < 4; i2++) {
        float lo[8], hi[8];
#pragma unroll
        for (int j = 0; j < 8; j++) {
            float2 f = unpack2(acc[i2][j]);
            lo[j] = f.x + bb[j];
            hi[j] = f.y + bb[j];
        }
        int r0 = ty * 8 + 2 * i2;
        *(float4*)(outp + (size_t)r0 * DK)           = make_float4(lo[0], lo[1], lo[2], lo[3]);
        *(float4*)(outp + (size_t)r0 * DK + 4)       = make_float4(lo[4], lo[5], lo[6], lo[7]);
        *(float4*)(outp + (size_t)(r0 + 1) * DK)     = make_float4(hi[0], hi[1], hi[2], hi[3]);
        *(float4*)(outp + (size_t)(r0 + 1) * DK + 4) = make_float4(hi[4], hi[5], hi[6], hi[7]);
    }
}

// ---------------------------------------------------------------------------
// Kernel 2: flash attention per (b,h, 64-query tile), f32x2 inner products.
// ---------------------------------------------------------------------------
__global__ __launch_bounds__(256) void flash_kernel()
{
    extern __shared__ float sm[];
    float* Qt = sm;                  // [64][68] transposed: Qt[d*68 + row]
    float* Kt = sm + 64 * 68;        // [64][68] transposed: Kt[d*68 + key]; reused as P[key*68 + row]
    float* Vs = sm + 2 * 64 * 68;    // [64][68] natural: Vs[s*68 + d]

    int bh = blockIdx.y;
    int t0 = blockIdx.x * 64;
    const float* Qp = g_Qh + (size_t)bh * TKN * DK;
    const float* Kp = g_Kh + (size_t)bh * TKN * DK;
    const float* Vp = g_Vh + (size_t)bh * TKN * DK;

    int tid = threadIdx.x;
    int ty = tid >> 4, tx = tid & 15;
    int lrow = tid >> 4;   // loader row base 0..15
    int kg = tid & 15;     // loader float4 group 0..15

    // Load Q tile transposed, pre-scaled by 1/sqrt(64)
#pragma unroll
    for (int m = 0; m < 4; m++) {
        int row = lrow + m * 16;
        float4 v = *(const float4*)(Qp + (size_t)(t0 + row) * DK + kg * 4);
        Qt[(kg * 4 + 0) * 68 + row] = v.x * 0.125f;
        Qt[(kg * 4 + 1) * 68 + row] = v.y * 0.125f;
        Qt[(kg * 4 + 2) * 68 + row] = v.z * 0.125f;
        Qt[(kg * 4 + 3) * 68 + row] = v.w * 0.125f;
    }

    float m_i[4], l_i[4];
    u64t O2[2][4];
#pragma unroll
    for (int i = 0; i < 4; i++) { m_i[i] = -1e30f; l_i[i] = 0.0f; }
#pragma unroll
    for (int i2 = 0; i2 < 2; i2++)
#pragma unroll
        for (int j = 0; j < 4; j++) O2[i2][j] = 0ULL;

    for (int s0 = 0; s0 < TKN; s0 += 64) {
        __syncthreads();   // previous P/V fully consumed
#pragma unroll
        for (int m = 0; m < 4; m++) {
            int row = lrow + m * 16;
            float4 kv = *(const float4*)(Kp + (size_t)(s0 + row) * DK + kg * 4);
            Kt[(kg * 4 + 0) * 68 + row] = kv.x;
            Kt[(kg * 4 + 1) * 68 + row] = kv.y;
            Kt[(kg * 4 + 2) * 68 + row] = kv.z;
            Kt[(kg * 4 + 3) * 68 + row] = kv.w;
            float4 vv = *(const float4*)(Vp + (size_t)(s0 + row) * DK + kg * 4);
            *(float4*)&Vs[row * 68 + kg * 4] = vv;
        }
        __syncthreads();

        // S = Q K^T : pairs along query rows
        u64t S2[2][4];
#pragma unroll
        for (int i2 = 0; i2 < 2; i2++)
#pragma unroll
            for (int j = 0; j < 4; j++) S2[i2][j] = 0ULL;
#pragma unroll 8
        for (int kk = 0; kk < 64; kk++) {
            float4 aq = *(const float4*)&Qt[kk * 68 + ty * 4];
            float4 bk4 = *(const float4*)&Kt[kk * 68 + tx * 4];
            u64t qa0 = pack2(aq.x, aq.y);
            u64t qa1 = pack2(aq.z, aq.w);
            float bf[4] = { bk4.x, bk4.y, bk4.z, bk4.w };
#pragma unroll
            for (int j = 0; j < 4; j++) {
                u64t bp = pack2(bf[j], bf[j]);
                fma2(S2[0][j], qa0, bp);
                fma2(S2[1][j], qa1, bp);
            }
        }

        float S[4][4];
#pragma unroll
        for (int i2 = 0; i2 < 2; i2++)
#pragma unroll
            for (int j = 0; j < 4; j++) {
                float2 f = unpack2(S2[i2][j]);
                S[2 * i2][j] = f.x;
                S[2 * i2 + 1][j] = f.y;
            }

        // online softmax update (rows spread over 16 tx lanes)
        float corr[4];
#pragma unroll
        for (int i = 0; i < 4; i++) {
            float mt = fmaxf(fmaxf(S[i][0], S[i][1]), fmaxf(S[i][2], S[i][3]));
            mt = fmaxf(mt, __shfl_xor_sync(0xffffffffu, mt, 1));
            mt = fmaxf(mt, __shfl_xor_sync(0xffffffffu, mt, 2));
            mt = fmaxf(mt, __shfl_xor_sync(0xffffffffu, mt, 4));
            mt = fmaxf(mt, __shfl_xor_sync(0xffffffffu, mt, 8));
            float mnew = fmaxf(m_i[i], mt);
            corr[i] = __expf(m_i[i] - mnew);
            float rs = 0.0f;
#pragma unroll
            for (int j = 0; j < 4; j++) {
                S[i][j] = __expf(S[i][j] - mnew);
                rs += S[i][j];
            }
            rs += __shfl_xor_sync(0xffffffffu, rs, 1);
            rs += __shfl_xor_sync(0xffffffffu, rs, 2);
            rs += __shfl_xor_sync(0xffffffffu, rs, 4);
            rs += __shfl_xor_sync(0xffffffffu, rs, 8);
            l_i[i] = l_i[i] * corr[i] + rs;
            m_i[i] = mnew;
        }
        // rescale O (packed pairs along rows)
#pragma unroll
        for (int i2 = 0; i2 < 2; i2++) {
            u64t c2 = pack2(corr[2 * i2], corr[2 * i2 + 1]);
#pragma unroll
            for (int j = 0; j < 4; j++) mul2(O2[i2][j], c2);
        }

        __syncthreads();   // everyone done reading Kt
        // store P transposed: Pt[key][row] in Kt's storage (64-bit row-pair stores)
#pragma unroll
        for (int i2 = 0; i2 < 2; i2++)
#pragma unroll
            for (int j = 0; j < 4; j++) {
                u64t pp = pack2(S[2 * i2][j], S[2 * i2 + 1][j]);
                *(u64t*)&Kt[(tx * 4 + j) * 68 + ty * 4 + 2 * i2] = pp;
            }
        __syncthreads();

        // O += P^T-layout @ V : pairs along rows come from one LDS.128
#pragma unroll 8
        for (int s = 0; s < 64; s++) {
            float4 pr4 = *(const float4*)&Kt[s * 68 + ty * 4];
            float4 vv = *(const float4*)&Vs[s * 68 + tx * 4];
            u64t pp0 = pack2(pr4.x, pr4.y);
            u64t pp1 = pack2(pr4.z, pr4.w);
            float vf[4] = { vv.x, vv.y, vv.z, vv.w };
#pragma unroll
            for (int j = 0; j < 4; j++) {
                u64t vp = pack2(vf[j], vf[j]);
                fma2(O2[0][j], pp0, vp);
                fma2(O2[1][j], pp1, vp);
            }
        }
    }

    float* cp = g_ctx + (size_t)bh * TKN * DK;
#pragma unroll
    for (int i2 = 0; i2 < 2; i2++) {
        float lo[4], hi[4];
#pragma unroll
        for (int j = 0; j < 4; j++) {
            float2 f = unpack2(O2[i2][j]);
            lo[j] = f.x; hi[j] = f.y;
        }
        int r0 = 2 * i2, r1 = 2 * i2 + 1;
        float inv0 = 1.0f / l_i[r0], inv1 = 1.0f / l_i[r1];
        *(float4*)(cp + (size_t)(t0 + ty * 4 + r0) * DK + tx * 4) =
            make_float4(lo[0] * inv0, lo[1] * inv0, lo[2] * inv0, lo[3] * inv0);
        *(float4*)(cp + (size_t)(t0 + ty * 4 + r1) * DK + tx * 4) =
            make_float4(hi[0] * inv1, hi[1] * inv1, hi[2] * inv1, hi[3] * inv1);
    }
}

// ---------------------------------------------------------------------------
// Kernel 3: output projection. X = flat ctx [4096][1024] (reference's .view is
// a plain flat reinterpretation). out[n,j] = sum_d X[n,d]*Wo[j,d] + bo[j].
// Tile 128x128, BK=16, 256 thr, 8x8/thread. grid (DM/128, 4096/128).
// ---------------------------------------------------------------------------
__global__ __launch_bounds__(256) void outproj_kernel(
    const float* __restrict__ Wo, const float* __restrict__ bo, float* __restrict__ out)
{
    __shared__ float At[16][132];   // transposed X tile: At[d][n]
    __shared__ float Bt[16][132];   // transposed Wo tile: Bt[d][j]

    int j0 = blockIdx.x * 128;
    int m0 = blockIdx.y * 128;
    int tid = threadIdx.x;
    int ty = tid >> 4, tx = tid & 15;
    int ar = tid >> 2, ac = tid & 3;

    const float* X = g_ctx;   // flat [4096][1024]

    u64t acc[4][8];
#pragma unroll
    for (int i = 0; i < 4; i++)
#pragma unroll
        for (int j = 0; j < 8; j++) acc[i][j] = 0ULL;

    for (int d0 = 0; d0 < DM; d0 += 16) {
        float4 a4  = *(const float4*)(X  + (size_t)(m0 + ar) * DM + d0 + ac * 4);
        float4 a4b = *(const float4*)(X  + (size_t)(m0 + ar + 64) * DM + d0 + ac * 4);
        float4 w4  = *(const float4*)(Wo + (size_t)(j0 + ar) * DM + d0 + ac * 4);
        float4 w4b = *(const float4*)(Wo + (size_t)(j0 + ar + 64) * DM + d0 + ac * 4);
        At[ac * 4 + 0][ar] = a4.x;  At[ac * 4 + 0][ar + 64] = a4b.x;
        At[ac * 4 + 1][ar] = a4.y;  At[ac * 4 + 1][ar + 64] = a4b.y;
        At[ac * 4 + 2][ar] = a4.z;  At[ac * 4 + 2][ar + 64] = a4b.z;
        At[ac * 4 + 3][ar] = a4.w;  At[ac * 4 + 3][ar + 64] = a4b.w;
        Bt[ac * 4 + 0][ar] = w4.x;  Bt[ac * 4 + 0][ar + 64] = w4b.x;
        Bt[ac * 4 + 1][ar] = w4.y;  Bt[ac * 4 + 1][ar + 64] = w4b.y;
        Bt[ac * 4 + 2][ar] = w4.z;  Bt[ac * 4 + 2][ar + 64] = w4b.z;
        Bt[ac * 4 + 3][ar] = w4.w;  Bt[ac * 4 + 3][ar + 64] = w4b.w;
        __syncthreads();
#pragma unroll
        for (int kk = 0; kk < 16; kk++) {
            float4 a0 = *(const float4*)&At[kk][ty * 8];
            float4 a1 = *(const float4*)&At[kk][ty * 8 + 4];
            float4 b0 = *(const float4*)&Bt[kk][tx * 8];
            float4 b1 = *(const float4*)&Bt[kk][tx * 8 + 4];
            u64t ap[4] = { pack2(a0.x, a0.y), pack2(a0.z, a0.w),
                           pack2(a1.x, a1.y), pack2(a1.z, a1.w) };
            float bf[8] = { b0.x, b0.y, b0.z, b0.w, b1.x, b1.y, b1.z, b1.w };
#pragma unroll
            for (int j = 0; j < 8; j++) {
                u64t bp = pack2(bf[j], bf[j]);
#pragma unroll
                for (int i = 0; i < 4; i++) fma2(acc[i][j], ap[i], bp);
            }
        }
        __syncthreads();
    }

    float bb[8];
#pragma unroll
    for (int j = 0; j < 8; j++) bb[j] = bo[j0 + tx * 8 + j];

    float* outp = out + (size_t)m0 * DM + j0 + tx * 8;
#pragma unroll
    for (int i2 = 0; i2 < 4; i2++) {
        float lo[8], hi[8];
#pragma unroll
        for (int j = 0; j < 8; j++) {
            float2 f = unpack2(acc[i2][j]);
            lo[j] = f.x + bb[j];
            hi[j] = f.y + bb[j];
        }
        int r0 = ty * 8 + 2 * i2;
        *(float4*)(outp + (size_t)r0 * DM)           = make_float4(lo[0], lo[1], lo[2], lo[3]);
        *(float4*)(outp + (size_t)r0 * DM + 4)       = make_float4(lo[4], lo[5], lo[6], lo[7]);
        *(float4*)(outp + (size_t)(r0 + 1) * DM)     = make_float4(hi[0], hi[1], hi[2], hi[3]);
        *(float4*)(outp + (size_t)(r0 + 1) * DM + 4) = make_float4(hi[4], hi[5], hi[6], hi[7]);
    }
}

// ---------------------------------------------------------------------------
extern "C" void kernel_launch(void* const* d_in, const int* in_sizes, int n_in,
                              void* d_out, int out_size)
{
    const float* Q  = (const float*)d_in[0];
    const float* K  = (const float*)d_in[1];
    const float* V  = (const float*)d_in[2];
    const float* Wq = (const float*)d_in[3];
    const float* bq = (const float*)d_in[4];
    const float* Wk = (const float*)d_in[5];
    const float* bk = (const float*)d_in[6];
    const float* Wv = (const float*)d_in[7];
    const float* bv = (const float*)d_in[8];
    const float* Wo = (const float*)d_in[9];
    const float* bo = (const float*)d_in[10];
    float* out = (float*)d_out;

    // 3 * 64 * 68 * 4 bytes = 52224 (> 48KB default) — idempotent, capture-safe.
    cudaFuncSetAttribute(flash_kernel, cudaFuncAttributeMaxDynamicSharedMemorySize, 52224);

    dim3 g1(TKN / 128, (B_SZ * HEADS) / 2, 3);
    proj_kernel<<<g1, 256>>>(Q, K, V, Wq, bq, Wk, bk, Wv, bv);

    dim3 g2(TKN / 64, B_SZ * HEADS);
    flash_kernel<<<g2, 256, 52224>>>();

    dim3 g3(DM / 128, (B_SZ * TKN) / 128);
    outproj_kernel<<<g3, 256>>>(Wo, bo, out);
}

// round 3
// speedup vs baseline: 1.1406x; 1.0862x over previous
#include <cuda_runtime.h>
#include <cstdint>

#define B_SZ  2
#define HEADS 16
#define TKN   2048
#define DM    1024
#define DK    64

typedef unsigned long long u64t;

// ---- packed f32x2 helpers (used by flash kernel) ----
__device__ __forceinline__ u64t pack2(float lo, float hi) {
    u64t r; asm("mov.b64 %0, {%1,%2};" : "=l"(r) : "f"(lo), "f"(hi)); return r;
}
__device__ __forceinline__ void fma2(u64t& d, u64t a, u64t b) {
    asm("fma.rn.f32x2 %0, %1, %2, %0;" : "+l"(d) : "l"(a), "l"(b));
}
__device__ __forceinline__ void mul2(u64t& d, u64t a) {
    asm("mul.rn.f32x2 %0, %0, %1;" : "+l"(d) : "l"(a));
}
__device__ __forceinline__ float2 unpack2(u64t v) {
    float2 r; asm("mov.b64 {%0,%1}, %2;" : "=f"(r.x), "=f"(r.y) : "l"(v)); return r;
}

// ---- tf32 mma.sync helpers ----
__device__ __forceinline__ uint32_t f2tf(float x) {
    uint32_t r; asm("cvt.rna.tf32.f32 %0, %1;" : "=r"(r) : "f"(x)); return r;
}
// split x into tf32 hi + tf32 lo (hi exact in f32, lo = x - hi exact)
__device__ __forceinline__ void tfsplit(float x, uint32_t& hi, uint32_t& lo) {
    hi = f2tf(x);
    float hf = __uint_as_float(hi);
    lo = f2tf(x - hf);
}
__device__ __forceinline__ void mma8(float* d,
    uint32_t a0, uint32_t a1, uint32_t a2, uint32_t a3, uint32_t b0, uint32_t b1) {
    asm("mma.sync.aligned.m16n8k8.row.col.f32.tf32.tf32.f32 "
        "{%0,%1,%2,%3},{%4,%5,%6,%7},{%8,%9},{%0,%1,%2,%3};"
        : "+f"(d[0]), "+f"(d[1]), "+f"(d[2]), "+f"(d[3])
        : "r"(a0), "r"(a1), "r"(a2), "r"(a3), "r"(b0), "r"(b1));
}

// Scratch (allocation-free rule: __device__ globals)
__device__ float g_Qh[B_SZ * HEADS * TKN * DK];
__device__ float g_Kh[B_SZ * HEADS * TKN * DK];
__device__ float g_Vh[B_SZ * HEADS * TKN * DK];
__device__ float g_ctx[B_SZ * HEADS * TKN * DK];

// ---------------------------------------------------------------------------
// Kernel 1: fused per-head Q/K/V projections via split-tf32 mma.sync.
// Block tile: M=128 (t rows), N=128 (2 heads x 64), K-chunk 32.
// 8 warps as 4(M) x 2(N); warp tile 32x64 = 2 Mtiles x 8 Ntiles of m16n8.
// grid = (T/128, B*8, 3)
// ---------------------------------------------------------------------------
__global__ __launch_bounds__(256) void proj_kernel(
    const float* __restrict__ Q, const float* __restrict__ K, const float* __restrict__ V,
    const float* __restrict__ Wq, const float* __restrict__ bq,
    const float* __restrict__ Wk, const float* __restrict__ bk,
    const float* __restrict__ Wv, const float* __restrict__ bv)
{
    __shared__ __align__(16) float Xs[128][36];   // X tile [row][k], pad->conflict-free frags
    __shared__ __align__(16) float Ws[32][136];   // W tile [k][col(2 heads)], pad 8
    __shared__ float sBias[128];

    const float* X; const float* W; const float* bias; float* out;
    int z = blockIdx.z;
    if (z == 0)      { X = Q; W = Wq; bias = bq; out = g_Qh; }
    else if (z == 1) { X = K; W = Wk; bias = bk; out = g_Kh; }
    else             { X = V; W = Wv; bias = bv; out = g_Vh; }

    int y = blockIdx.y;               // 0..15
    int b = y >> 3, h0 = (y & 7) * 2;
    int t0 = blockIdx.x * 128;

    const float* Xb = X + ((size_t)b * TKN + t0) * DM;
    const float* W0 = W + (size_t)h0 * DM * DK;

    int tid = threadIdx.x;
    int lane = tid & 31, w = tid >> 5;
    int wm = w & 3, wn = w >> 2;       // warp coords: 4(M) x 2(N)
    int g = lane >> 2, tg = lane & 3;  // groupID, threadInGroup

    if (tid < 128) sBias[tid] = bias[h0 * DK + tid];

    float acc[2][8][4];
#pragma unroll
    for (int mt = 0; mt < 2; mt++)
#pragma unroll
        for (int nt = 0; nt < 8; nt++)
#pragma unroll
            for (int q = 0; q < 4; q++) acc[mt][nt][q] = 0.0f;

    for (int d0 = 0; d0 < DM; d0 += 32) {
        // stage X tile: 128 rows x 32 cols
#pragma unroll
        for (int i = 0; i < 4; i++) {
            int idx = tid + i * 256;
            int r = idx >> 3, c4 = idx & 7;
            float4 v = *(const float4*)(Xb + (size_t)r * DM + d0 + c4 * 4);
            *(float4*)&Xs[r][c4 * 4] = v;
        }
        // stage W tile: 32 k-rows x 128 cols (two heads side by side)
#pragma unroll
        for (int i = 0; i < 4; i++) {
            int idx = tid + i * 256;
            int k = idx >> 5, c4 = idx & 31;
            const float* src = W0 + (c4 < 16 ? 0 : (size_t)DM * DK)
                               + (size_t)(d0 + k) * DK + (c4 & 15) * 4;
            *(float4*)&Ws[k][c4 * 4] = *(const float4*)src;
        }
        __syncthreads();

#pragma unroll
        for (int kk = 0; kk < 32; kk += 8) {
            uint32_t ahi[2][4], alo[2][4];
#pragma unroll
            for (int mt = 0; mt < 2; mt++) {
                int rb = wm * 32 + mt * 16;
                tfsplit(Xs[rb + g][kk + tg],         ahi[mt][0], alo[mt][0]);
                tfsplit(Xs[rb + g + 8][kk + tg],     ahi[mt][1], alo[mt][1]);
                tfsplit(Xs[rb + g][kk + tg + 4],     ahi[mt][2], alo[mt][2]);
                tfsplit(Xs[rb + g + 8][kk + tg + 4], ahi[mt][3], alo[mt][3]);
            }
#pragma unroll
            for (int nh = 0; nh < 2; nh++) {
                uint32_t bhi[4][2], blo[4][2];
#pragma unroll
                for (int nt = 0; nt < 4; nt++) {
                    int nb = wn * 64 + (nh * 4 + nt) * 8;
                    tfsplit(Ws[kk + tg][nb + g],     bhi[nt][0], blo[nt][0]);
                    tfsplit(Ws[kk + tg + 4][nb + g], bhi[nt][1], blo[nt][1]);
                }
                // three passes: same-accumulator MMAs separated by 8 issues
#pragma unroll
                for (int nt = 0; nt < 4; nt++)
#pragma unroll
                    for (int mt = 0; mt < 2; mt++)
                        mma8(acc[mt][nh * 4 + nt], ahi[mt][0], ahi[mt][1], ahi[mt][2], ahi[mt][3],
                             bhi[nt][0], bhi[nt][1]);
#pragma unroll
                for (int nt = 0; nt < 4; nt++)
#pragma unroll
                    for (int mt = 0; mt < 2; mt++)
                        mma8(acc[mt][nh * 4 + nt], alo[mt][0], alo[mt][1], alo[mt][2], alo[mt][3],
                             bhi[nt][0], bhi[nt][1]);
#pragma unroll
                for (int nt = 0; nt < 4; nt++)
#pragma unroll
                    for (int mt = 0; mt < 2; mt++)
                        mma8(acc[mt][nh * 4 + nt], ahi[mt][0], ahi[mt][1], ahi[mt][2], ahi[mt][3],
                             blo[nt][0], blo[nt][1]);
            }
        }
        __syncthreads();
    }

    // epilogue: head = h0 + wn; local col = nt*8 + 2tg
    float* outh = out + ((size_t)(b * HEADS + h0 + wn) * TKN + t0) * DK;
#pragma unroll
    for (int mt = 0; mt < 2; mt++) {
        int r0 = wm * 32 + mt * 16 + g;
#pragma unroll
        for (int nt = 0; nt < 8; nt++) {
            int cl = nt * 8 + 2 * tg;
            float b0v = sBias[wn * 64 + cl], b1v = sBias[wn * 64 + cl + 1];
            *(float2*)(outh + (size_t)r0 * DK + cl) =
                make_float2(acc[mt][nt][0] + b0v, acc[mt][nt][1] + b1v);
            *(float2*)(outh + (size_t)(r0 + 8) * DK + cl) =
                make_float2(acc[mt][nt][2] + b0v, acc[mt][nt][3] + b1v);
        }
    }
}

// ---------------------------------------------------------------------------
// Kernel 2: flash attention per (b,h, 64-query tile) — unchanged from R2.
// ---------------------------------------------------------------------------
__global__ __launch_bounds__(256) void flash_kernel()
{
    extern __shared__ float sm[];
    float* Qt = sm;                  // [64][68] transposed
    float* Kt = sm + 64 * 68;        // [64][68] transposed; reused as P
    float* Vs = sm + 2 * 64 * 68;    // [64][68] natural

    int bh = blockIdx.y;
    int t0 = blockIdx.x * 64;
    const float* Qp = g_Qh + (size_t)bh * TKN * DK;
    const float* Kp = g_Kh + (size_t)bh * TKN * DK;
    const float* Vp = g_Vh + (size_t)bh * TKN * DK;

    int tid = threadIdx.x;
    int ty = tid >> 4, tx = tid & 15;
    int lrow = tid >> 4;
    int kg = tid & 15;

#pragma unroll
    for (int m = 0; m < 4; m++) {
        int row = lrow + m * 16;
        float4 v = *(const float4*)(Qp + (size_t)(t0 + row) * DK + kg * 4);
        Qt[(kg * 4 + 0) * 68 + row] = v.x * 0.125f;
        Qt[(kg * 4 + 1) * 68 + row] = v.y * 0.125f;
        Qt[(kg * 4 + 2) * 68 + row] = v.z * 0.125f;
        Qt[(kg * 4 + 3) * 68 + row] = v.w * 0.125f;
    }

    float m_i[4], l_i[4];
    u64t O2[2][4];
#pragma unroll
    for (int i = 0; i < 4; i++) { m_i[i] = -1e30f; l_i[i] = 0.0f; }
#pragma unroll
    for (int i2 = 0; i2 < 2; i2++)
#pragma unroll
        for (int j = 0; j < 4; j++) O2[i2][j] = 0ULL;

    for (int s0 = 0; s0 < TKN; s0 += 64) {
        __syncthreads();
#pragma unroll
        for (int m = 0; m < 4; m++) {
            int row = lrow + m * 16;
            float4 kv = *(const float4*)(Kp + (size_t)(s0 + row) * DK + kg * 4);
            Kt[(kg * 4 + 0) * 68 + row] = kv.x;
            Kt[(kg * 4 + 1) * 68 + row] = kv.y;
            Kt[(kg * 4 + 2) * 68 + row] = kv.z;
            Kt[(kg * 4 + 3) * 68 + row] = kv.w;
            float4 vv = *(const float4*)(Vp + (size_t)(s0 + row) * DK + kg * 4);
            *(float4*)&Vs[row * 68 + kg * 4] = vv;
        }
        __syncthreads();

        u64t S2[2][4];
#pragma unroll
        for (int i2 = 0; i2 < 2; i2++)
#pragma unroll
            for (int j = 0; j < 4; j++) S2[i2][j] = 0ULL;
#pragma unroll 8
        for (int kk = 0; kk < 64; kk++) {
            float4 aq = *(const float4*)&Qt[kk * 68 + ty * 4];
            float4 bk4 = *(const float4*)&Kt[kk * 68 + tx * 4];
            u64t qa0 = pack2(aq.x, aq.y);
            u64t qa1 = pack2(aq.z, aq.w);
            float bf[4] = { bk4.x, bk4.y, bk4.z, bk4.w };
#pragma unroll
            for (int j = 0; j < 4; j++) {
                u64t bp = pack2(bf[j], bf[j]);
                fma2(S2[0][j], qa0, bp);
                fma2(S2[1][j], qa1, bp);
            }
        }

        float S[4][4];
#pragma unroll
        for (int i2 = 0; i2 < 2; i2++)
#pragma unroll
            for (int j = 0; j < 4; j++) {
                float2 f = unpack2(S2[i2][j]);
                S[2 * i2][j] = f.x;
                S[2 * i2 + 1][j] = f.y;
            }

        float corr[4];
#pragma unroll
        for (int i = 0; i < 4; i++) {
            float mt = fmaxf(fmaxf(S[i][0], S[i][1]), fmaxf(S[i][2], S[i][3]));
            mt = fmaxf(mt, __shfl_xor_sync(0xffffffffu, mt, 1));
            mt = fmaxf(mt, __shfl_xor_sync(0xffffffffu, mt, 2));
            mt = fmaxf(mt, __shfl_xor_sync(0xffffffffu, mt, 4));
            mt = fmaxf(mt, __shfl_xor_sync(0xffffffffu, mt, 8));
            float mnew = fmaxf(m_i[i], mt);
            corr[i] = __expf(m_i[i] - mnew);
            float rs = 0.0f;
#pragma unroll
            for (int j = 0; j < 4; j++) {
                S[i][j] = __expf(S[i][j] - mnew);
                rs += S[i][j];
            }
            rs += __shfl_xor_sync(0xffffffffu, rs, 1);
            rs += __shfl_xor_sync(0xffffffffu, rs, 2);
            rs += __shfl_xor_sync(0xffffffffu, rs, 4);
            rs += __shfl_xor_sync(0xffffffffu, rs, 8);
            l_i[i] = l_i[i] * corr[i] + rs;
            m_i[i] = mnew;
        }
#pragma unroll
        for (int i2 = 0; i2 < 2; i2++) {
            u64t c2 = pack2(corr[2 * i2], corr[2 * i2 + 1]);
#pragma unroll
            for (int j = 0; j < 4; j++) mul2(O2[i2][j], c2);
        }

        __syncthreads();
#pragma unroll
        for (int i2 = 0; i2 < 2; i2++)
#pragma unroll
            for (int j = 0; j < 4; j++) {
                u64t pp = pack2(S[2 * i2][j], S[2 * i2 + 1][j]);
                *(u64t*)&Kt[(tx * 4 + j) * 68 + ty * 4 + 2 * i2] = pp;
            }
        __syncthreads();

#pragma unroll 8
        for (int s = 0; s < 64; s++) {
            float4 pr4 = *(const float4*)&Kt[s * 68 + ty * 4];
            float4 vv = *(const float4*)&Vs[s * 68 + tx * 4];
            u64t pp0 = pack2(pr4.x, pr4.y);
            u64t pp1 = pack2(pr4.z, pr4.w);
            float vf[4] = { vv.x, vv.y, vv.z, vv.w };
#pragma unroll
            for (int j = 0; j < 4; j++) {
                u64t vp = pack2(vf[j], vf[j]);
                fma2(O2[0][j], pp0, vp);
                fma2(O2[1][j], pp1, vp);
            }
        }
    }

    float* cp = g_ctx + (size_t)bh * TKN * DK;
#pragma unroll
    for (int i2 = 0; i2 < 2; i2++) {
        float lo[4], hi[4];
#pragma unroll
        for (int j = 0; j < 4; j++) {
            float2 f = unpack2(O2[i2][j]);
            lo[j] = f.x; hi[j] = f.y;
        }
        int r0 = 2 * i2, r1 = 2 * i2 + 1;
        float inv0 = 1.0f / l_i[r0], inv1 = 1.0f / l_i[r1];
        *(float4*)(cp + (size_t)(t0 + ty * 4 + r0) * DK + tx * 4) =
            make_float4(lo[0] * inv0, lo[1] * inv0, lo[2] * inv0, lo[3] * inv0);
        *(float4*)(cp + (size_t)(t0 + ty * 4 + r1) * DK + tx * 4) =
            make_float4(hi[0] * inv1, hi[1] * inv1, hi[2] * inv1, hi[3] * inv1);
    }
}

// ---------------------------------------------------------------------------
// Kernel 3: output projection via split-tf32 mma.sync.
// out[n,j] = sum_d ctx[n,d] * Wo[j,d] + bo[j]; ctx read flat [4096][1024].
// Same 128x128 tile / 8-warp structure. B frags come from Wo rows (row-major
// [j][d] == col-major [d][j] exactly as mma wants).
// ---------------------------------------------------------------------------
__global__ __launch_bounds__(256) void outproj_kernel(
    const float* __restrict__ Wo, const float* __restrict__ bo, float* __restrict__ out)
{
    __shared__ __align__(16) float Xs[128][36];    // ctx tile [n][d]
    __shared__ __align__(16) float Wos[128][36];   // Wo tile  [j][d]
    __shared__ float sBias[128];

    int j0 = blockIdx.x * 128;
    int m0 = blockIdx.y * 128;

    int tid = threadIdx.x;
    int lane = tid & 31, w = tid >> 5;
    int wm = w & 3, wn = w >> 2;
    int g = lane >> 2, tg = lane & 3;

    if (tid < 128) sBias[tid] = bo[j0 + tid];

    const float* X = g_ctx;

    float acc[2][8][4];
#pragma unroll
    for (int mt = 0; mt < 2; mt++)
#pragma unroll
        for (int nt = 0; nt < 8; nt++)
#pragma unroll
            for (int q = 0; q < 4; q++) acc[mt][nt][q] = 0.0f;

    for (int d0 = 0; d0 < DM; d0 += 32) {
#pragma unroll
        for (int i = 0; i < 4; i++) {
            int idx = tid + i * 256;
            int r = idx >> 3, c4 = idx & 7;
            *(float4*)&Xs[r][c4 * 4] =
                *(const float4*)(X + (size_t)(m0 + r) * DM + d0 + c4 * 4);
            *(float4*)&Wos[r][c4 * 4] =
                *(const float4*)(Wo + (size_t)(j0 + r) * DM + d0 + c4 * 4);
        }
        __syncthreads();

#pragma unroll
        for (int kk = 0; kk < 32; kk += 8) {
            uint32_t ahi[2][4], alo[2][4];
#pragma unroll
            for (int mt = 0; mt < 2; mt++) {
                int rb = wm * 32 + mt * 16;
                tfsplit(Xs[rb + g][kk + tg],         ahi[mt][0], alo[mt][0]);
                tfsplit(Xs[rb + g + 8][kk + tg],     ahi[mt][1], alo[mt][1]);
                tfsplit(Xs[rb + g][kk + tg + 4],     ahi[mt][2], alo[mt][2]);
                tfsplit(Xs[rb + g + 8][kk + tg + 4], ahi[mt][3], alo[mt][3]);
            }
#pragma unroll
            for (int nh = 0; nh < 2; nh++) {
                uint32_t bhi[4][2], blo[4][2];
#pragma unroll
                for (int nt = 0; nt < 4; nt++) {
                    int nb = wn * 64 + (nh * 4 + nt) * 8;
                    tfsplit(Wos[nb + g][kk + tg],     bhi[nt][0], blo[nt][0]);
                    tfsplit(Wos[nb + g][kk + tg + 4], bhi[nt][1], blo[nt][1]);
                }
#pragma unroll
                for (int nt = 0; nt < 4; nt++)
#pragma unroll
                    for (int mt = 0; mt < 2; mt++)
                        mma8(acc[mt][nh * 4 + nt], ahi[mt][0], ahi[mt][1], ahi[mt][2], ahi[mt][3],
                             bhi[nt][0], bhi[nt][1]);
#pragma unroll
                for (int nt = 0; nt < 4; nt++)
#pragma unroll
                    for (int mt = 0; mt < 2; mt++)
                        mma8(acc[mt][nh * 4 + nt], alo[mt][0], alo[mt][1], alo[mt][2], alo[mt][3],
                             bhi[nt][0], bhi[nt][1]);
#pragma unroll
                for (int nt = 0; nt < 4; nt++)
#pragma unroll
                    for (int mt = 0; mt < 2; mt++)
                        mma8(acc[mt][nh * 4 + nt], ahi[mt][0], ahi[mt][1], ahi[mt][2], ahi[mt][3],
                             blo[nt][0], blo[nt][1]);
            }
        }
        __syncthreads();
    }

#pragma unroll
    for (int mt = 0; mt < 2; mt++) {
        int r0 = m0 + wm * 32 + mt * 16 + g;
#pragma unroll
        for (int nt = 0; nt < 8; nt++) {
            int cl = wn * 64 + nt * 8 + 2 * tg;
            float b0v = sBias[cl], b1v = sBias[cl + 1];
            *(float2*)(out + (size_t)r0 * DM + j0 + cl) =
                make_float2(acc[mt][nt][0] + b0v, acc[mt][nt][1] + b1v);
            *(float2*)(out + (size_t)(r0 + 8) * DM + j0 + cl) =
                make_float2(acc[mt][nt][2] + b0v, acc[mt][nt][3] + b1v);
        }
    }
}

// ---------------------------------------------------------------------------
extern "C" void kernel_launch(void* const* d_in, const int* in_sizes, int n_in,
                              void* d_out, int out_size)
{
    const float* Q  = (const float*)d_in[0];
    const float* K  = (const float*)d_in[1];
    const float* V  = (const float*)d_in[2];
    const float* Wq = (const float*)d_in[3];
    const float* bq = (const float*)d_in[4];
    const float* Wk = (const float*)d_in[5];
    const float* bk = (const float*)d_in[6];
    const float* Wv = (const float*)d_in[7];
    const float* bv = (const float*)d_in[8];
    const float* Wo = (const float*)d_in[9];
    const float* bo = (const float*)d_in[10];
    float* out = (float*)d_out;

    cudaFuncSetAttribute(flash_kernel, cudaFuncAttributeMaxDynamicSharedMemorySize, 52224);

    dim3 g1(TKN / 128, B_SZ * 8, 3);
    proj_kernel<<<g1, 256>>>(Q, K, V, Wq, bq, Wk, bk, Wv, bv);

    dim3 g2(TKN / 64, B_SZ * HEADS);
    flash_kernel<<<g2, 256, 52224>>>();

    dim3 g3(DM / 128, (B_SZ * TKN) / 128);
    outproj_kernel<<<g3, 256>>>(Wo, bo, out);
}

// round 4
// speedup vs baseline: 1.9999x; 1.7535x over previous
#include <cuda_runtime.h>
#include <cuda_fp16.h>
#include <cstdint>

#define B_SZ  2
#define HEADS 16
#define TKN   2048
#define DM    1024
#define DK    64

typedef unsigned long long u64t;

// ---- tf32 mma.sync helpers (proj / outproj) ----
__device__ __forceinline__ uint32_t f2tf(float x) {
    uint32_t r; asm("cvt.rna.tf32.f32 %0, %1;" : "=r"(r) : "f"(x)); return r;
}
__device__ __forceinline__ void tfsplit(float x, uint32_t& hi, uint32_t& lo) {
    hi = f2tf(x);
    float hf = __uint_as_float(hi);
    lo = f2tf(x - hf);
}
__device__ __forceinline__ void mma8(float* d,
    uint32_t a0, uint32_t a1, uint32_t a2, uint32_t a3, uint32_t b0, uint32_t b1) {
    asm("mma.sync.aligned.m16n8k8.row.col.f32.tf32.tf32.f32 "
        "{%0,%1,%2,%3},{%4,%5,%6,%7},{%8,%9},{%0,%1,%2,%3};"
        : "+f"(d[0]), "+f"(d[1]), "+f"(d[2]), "+f"(d[3])
        : "r"(a0), "r"(a1), "r"(a2), "r"(a3), "r"(b0), "r"(b1));
}

// ---- fp16 mma / ldmatrix / f16x2 helpers (flash) ----
__device__ __forceinline__ uint32_t cvta_s(const void* p) {
    return (uint32_t)__cvta_generic_to_shared(p);
}
__device__ __forceinline__ void ldm4(uint32_t* r, uint32_t a) {
    asm volatile("ldmatrix.sync.aligned.m8n8.x4.shared.b16 {%0,%1,%2,%3},[%4];"
        : "=r"(r[0]), "=r"(r[1]), "=r"(r[2]), "=r"(r[3]) : "r"(a));
}
__device__ __forceinline__ void ldm4t(uint32_t* r, uint32_t a) {
    asm volatile("ldmatrix.sync.aligned.m8n8.x4.trans.shared.b16 {%0,%1,%2,%3},[%4];"
        : "=r"(r[0]), "=r"(r[1]), "=r"(r[2]), "=r"(r[3]) : "r"(a));
}
__device__ __forceinline__ void mmah(float* d, uint32_t a0, uint32_t a1, uint32_t a2,
                                     uint32_t a3, uint32_t b0, uint32_t b1) {
    asm("mma.sync.aligned.m16n8k16.row.col.f32.f16.f16.f32 "
        "{%0,%1,%2,%3},{%4,%5,%6,%7},{%8,%9},{%0,%1,%2,%3};"
        : "+f"(d[0]), "+f"(d[1]), "+f"(d[2]), "+f"(d[3])
        : "r"(a0), "r"(a1), "r"(a2), "r"(a3), "r"(b0), "r"(b1));
}
// pack two f32 -> f16x2 (hi goes to upper half, lo to lower half)
__device__ __forceinline__ uint32_t cvt2h(float hi, float lo) {
    uint32_t d; asm("cvt.rn.f16x2.f32 %0, %1, %2;" : "=r"(d) : "f"(hi), "f"(lo)); return d;
}
__device__ __forceinline__ uint32_t ex2h2(uint32_t x) {
    uint32_t d; asm("ex2.approx.f16x2 %0, %1;" : "=r"(d) : "r"(x)); return d;
}
__device__ __forceinline__ float ex2f(float x) {
    float d; asm("ex2.approx.ftz.f32 %0, %1;" : "=f"(d) : "f"(x)); return d;
}
__device__ __forceinline__ uint32_t hadd2u(uint32_t a, uint32_t b) {
    uint32_t d; asm("add.rn.f16x2 %0, %1, %2;" : "=r"(d) : "r"(a), "r"(b)); return d;
}
__device__ __forceinline__ float h2sumf(uint32_t h) {
    __half2 v = *(__half2*)&h;
    return __low2float(v) + __high2float(v);
}

// Scratch (allocation-free rule: __device__ globals)
__device__ __half g_Qh[B_SZ * HEADS * TKN * DK];   // pre-scaled by 1/8
__device__ __half g_Kh[B_SZ * HEADS * TKN * DK];
__device__ __half g_Vh[B_SZ * HEADS * TKN * DK];
__device__ float  g_ctx[B_SZ * HEADS * TKN * DK];

// ---------------------------------------------------------------------------
// Kernel 1: fused per-head Q/K/V projections via split-tf32 mma.sync.
// Writes f16 outputs (Q pre-scaled by 0.125).
// ---------------------------------------------------------------------------
__global__ __launch_bounds__(256) void proj_kernel(
    const float* __restrict__ Q, const float* __restrict__ K, const float* __restrict__ V,
    const float* __restrict__ Wq, const float* __restrict__ bq,
    const float* __restrict__ Wk, const float* __restrict__ bk,
    const float* __restrict__ Wv, const float* __restrict__ bv)
{
    __shared__ __align__(16) float Xs[128][36];
    __shared__ __align__(16) float Ws[32][136];
    __shared__ float sBias[128];

    const float* X; const float* W; const float* bias; __half* out; float oscale;
    int z = blockIdx.z;
    if (z == 0)      { X = Q; W = Wq; bias = bq; out = g_Qh; oscale = 0.125f; }
    else if (z == 1) { X = K; W = Wk; bias = bk; out = g_Kh; oscale = 1.0f; }
    else             { X = V; W = Wv; bias = bv; out = g_Vh; oscale = 1.0f; }

    int y = blockIdx.y;
    int b = y >> 3, h0 = (y & 7) * 2;
    int t0 = blockIdx.x * 128;

    const float* Xb = X + ((size_t)b * TKN + t0) * DM;
    const float* W0 = W + (size_t)h0 * DM * DK;

    int tid = threadIdx.x;
    int lane = tid & 31, w = tid >> 5;
    int wm = w & 3, wn = w >> 2;
    int g = lane >> 2, tg = lane & 3;

    if (tid < 128) sBias[tid] = bias[h0 * DK + tid];

    float acc[2][8][4];
#pragma unroll
    for (int mt = 0; mt < 2; mt++)
#pragma unroll
        for (int nt = 0; nt < 8; nt++)
#pragma unroll
            for (int q = 0; q < 4; q++) acc[mt][nt][q] = 0.0f;

    for (int d0 = 0; d0 < DM; d0 += 32) {
#pragma unroll
        for (int i = 0; i < 4; i++) {
            int idx = tid + i * 256;
            int r = idx >> 3, c4 = idx & 7;
            *(float4*)&Xs[r][c4 * 4] = *(const float4*)(Xb + (size_t)r * DM + d0 + c4 * 4);
        }
#pragma unroll
        for (int i = 0; i < 4; i++) {
            int idx = tid + i * 256;
            int k = idx >> 5, c4 = idx & 31;
            const float* src = W0 + (c4 < 16 ? 0 : (size_t)DM * DK)
                               + (size_t)(d0 + k) * DK + (c4 & 15) * 4;
            *(float4*)&Ws[k][c4 * 4] = *(const float4*)src;
        }
        __syncthreads();

#pragma unroll
        for (int kk = 0; kk < 32; kk += 8) {
            uint32_t ahi[2][4], alo[2][4];
#pragma unroll
            for (int mt = 0; mt < 2; mt++) {
                int rb = wm * 32 + mt * 16;
                tfsplit(Xs[rb + g][kk + tg],         ahi[mt][0], alo[mt][0]);
                tfsplit(Xs[rb + g + 8][kk + tg],     ahi[mt][1], alo[mt][1]);
                tfsplit(Xs[rb + g][kk + tg + 4],     ahi[mt][2], alo[mt][2]);
                tfsplit(Xs[rb + g + 8][kk + tg + 4], ahi[mt][3], alo[mt][3]);
            }
#pragma unroll
            for (int nh = 0; nh < 2; nh++) {
                uint32_t bhi[4][2], blo[4][2];
#pragma unroll
                for (int nt = 0; nt < 4; nt++) {
                    int nb = wn * 64 + (nh * 4 + nt) * 8;
                    tfsplit(Ws[kk + tg][nb + g],     bhi[nt][0], blo[nt][0]);
                    tfsplit(Ws[kk + tg + 4][nb + g], bhi[nt][1], blo[nt][1]);
                }
#pragma unroll
                for (int nt = 0; nt < 4; nt++)
#pragma unroll
                    for (int mt = 0; mt < 2; mt++)
                        mma8(acc[mt][nh * 4 + nt], ahi[mt][0], ahi[mt][1], ahi[mt][2], ahi[mt][3],
                             bhi[nt][0], bhi[nt][1]);
#pragma unroll
                for (int nt = 0; nt < 4; nt++)
#pragma unroll
                    for (int mt = 0; mt < 2; mt++)
                        mma8(acc[mt][nh * 4 + nt], alo[mt][0], alo[mt][1], alo[mt][2], alo[mt][3],
                             bhi[nt][0], bhi[nt][1]);
#pragma unroll
                for (int nt = 0; nt < 4; nt++)
#pragma unroll
                    for (int mt = 0; mt < 2; mt++)
                        mma8(acc[mt][nh * 4 + nt], ahi[mt][0], ahi[mt][1], ahi[mt][2], ahi[mt][3],
                             blo[nt][0], blo[nt][1]);
            }
        }
        __syncthreads();
    }

    __half* outh = out + ((size_t)(b * HEADS + h0 + wn) * TKN + t0) * DK;
#pragma unroll
    for (int mt = 0; mt < 2; mt++) {
        int r0 = wm * 32 + mt * 16 + g;
#pragma unroll
        for (int nt = 0; nt < 8; nt++) {
            int cl = nt * 8 + 2 * tg;
            float b0v = sBias[wn * 64 + cl], b1v = sBias[wn * 64 + cl + 1];
            *(__half2*)(outh + (size_t)r0 * DK + cl) =
                __floats2half2_rn((acc[mt][nt][0] + b0v) * oscale, (acc[mt][nt][1] + b1v) * oscale);
            *(__half2*)(outh + (size_t)(r0 + 8) * DK + cl) =
                __floats2half2_rn((acc[mt][nt][2] + b0v) * oscale, (acc[mt][nt][3] + b1v) * oscale);
        }
    }
}

// ---------------------------------------------------------------------------
// Kernel 2: flash attention, fp16 mma + f16x2 ex2.
// Block: 128 threads (4 warps). 64 queries/block, key chunks of 64.
// Warp w owns query rows w*16..w*16+15 (x all keys, all dk).
// ---------------------------------------------------------------------------
__global__ __launch_bounds__(128) void flash_kernel()
{
    __shared__ __half Qs[64][72];
    __shared__ __half Ks[64][72];
    __shared__ __half Vs[64][72];

    const float C = 1.4426950408889634f;   // log2(e)

    int bh = blockIdx.y;
    int t0 = blockIdx.x * 64;
    const __half* Qp = g_Qh + (size_t)bh * TKN * DK;
    const __half* Kp = g_Kh + (size_t)bh * TKN * DK;
    const __half* Vp = g_Vh + (size_t)bh * TKN * DK;

    int tid = threadIdx.x;
    int lane = tid & 31, w = tid >> 5;
    int g = lane >> 2, tg = lane & 3;

    // stage Q (64 rows x 128B)
#pragma unroll
    for (int i = 0; i < 4; i++) {
        int idx = i * 128 + tid;
        int r = idx >> 3, c = idx & 7;
        *(uint4*)&Qs[r][c * 8] = *(const uint4*)(Qp + (size_t)(t0 + r) * DK + c * 8);
    }
    __syncthreads();

    // Q a-fragments: 4 ksteps x 4 regs
    uint32_t Qa[4][4];
    {
        int qrow = w * 16 + ((lane >> 3) & 1) * 8 + (lane & 7);
        int qcol = (lane >> 4) * 8;
        uint32_t qbase = cvta_s(&Qs[qrow][qcol]);
#pragma unroll
        for (int ks = 0; ks < 4; ks++) ldm4(Qa[ks], qbase + ks * 32);
    }

    // lane-dependent ldmatrix bases for K (non-trans) and V (trans)
    uint32_t kbase = cvta_s(Ks) + (((lane & 7) * 72 + (lane >> 3) * 8) << 1);
    uint32_t vbase = cvta_s(Vs) + ((((lane >> 3) * 8 + (lane & 7)) * 72) << 1);

    float m0 = -1e30f, m1 = -1e30f, l0 = 0.0f, l1 = 0.0f;
    float O[8][4];
#pragma unroll
    for (int nt = 0; nt < 8; nt++)
#pragma unroll
        for (int q = 0; q < 4; q++) O[nt][q] = 0.0f;

    for (int s0 = 0; s0 < TKN; s0 += 64) {
        __syncthreads();
#pragma unroll
        for (int i = 0; i < 4; i++) {
            int idx = i * 128 + tid;
            int r = idx >> 3, c = idx & 7;
            *(uint4*)&Ks[r][c * 8] = *(const uint4*)(Kp + (size_t)(s0 + r) * DK + c * 8);
            *(uint4*)&Vs[r][c * 8] = *(const uint4*)(Vp + (size_t)(s0 + r) * DK + c * 8);
        }
        __syncthreads();

        // S = Q K^T  (16 rows x 64 keys per warp)
        float S[8][4];
#pragma unroll
        for (int nt = 0; nt < 8; nt++) {
#pragma unroll
            for (int q = 0; q < 4; q++) S[nt][q] = 0.0f;
            uint32_t bk[8];
            uint32_t ka = kbase + ((nt * 8 * 72) << 1);
            ldm4(bk,     ka);
            ldm4(bk + 4, ka + 64);
#pragma unroll
            for (int ks = 0; ks < 4; ks++)
                mmah(S[nt], Qa[ks][0], Qa[ks][1], Qa[ks][2], Qa[ks][3],
                     bk[2 * ks], bk[2 * ks + 1]);
        }

        // row max (row g -> c0,c1 ; row g+8 -> c2,c3)
        float mx0 = fmaxf(S[0][0], S[0][1]);
        float mx1 = fmaxf(S[0][2], S[0][3]);
#pragma unroll
        for (int nt = 1; nt < 8; nt++) {
            mx0 = fmaxf(mx0, fmaxf(S[nt][0], S[nt][1]));
            mx1 = fmaxf(mx1, fmaxf(S[nt][2], S[nt][3]));
        }
        mx0 = fmaxf(mx0, __shfl_xor_sync(0xffffffffu, mx0, 1));
        mx0 = fmaxf(mx0, __shfl_xor_sync(0xffffffffu, mx0, 2));
        mx1 = fmaxf(mx1, __shfl_xor_sync(0xffffffffu, mx1, 1));
        mx1 = fmaxf(mx1, __shfl_xor_sync(0xffffffffu, mx1, 2));

        float mn0 = fmaxf(m0, mx0), mn1 = fmaxf(m1, mx1);
        float corr0 = ex2f((m0 - mn0) * C);
        float corr1 = ex2f((m1 - mn1) * C);
        m0 = mn0; m1 = mn1;
        float mc0 = mn0 * C, mc1 = mn1 * C;

        // P = exp(S - m) in f16x2, laid out as mma a-fragments
        uint32_t P01[8], P23[8];
#pragma unroll
        for (int nt = 0; nt < 8; nt++) {
            P01[nt] = ex2h2(cvt2h(fmaf(S[nt][1], C, -mc0), fmaf(S[nt][0], C, -mc0)));
            P23[nt] = ex2h2(cvt2h(fmaf(S[nt][3], C, -mc1), fmaf(S[nt][2], C, -mc1)));
        }

        // row sums via HADD2 trees
        uint32_t s01 = hadd2u(hadd2u(hadd2u(P01[0], P01[1]), hadd2u(P01[2], P01[3])),
                              hadd2u(hadd2u(P01[4], P01[5]), hadd2u(P01[6], P01[7])));
        uint32_t s23 = hadd2u(hadd2u(hadd2u(P23[0], P23[1]), hadd2u(P23[2], P23[3])),
                              hadd2u(hadd2u(P23[4], P23[5]), hadd2u(P23[6], P23[7])));
        float rs0 = h2sumf(s01), rs1 = h2sumf(s23);
        rs0 += __shfl_xor_sync(0xffffffffu, rs0, 1);
        rs0 += __shfl_xor_sync(0xffffffffu, rs0, 2);
        rs1 += __shfl_xor_sync(0xffffffffu, rs1, 1);
        rs1 += __shfl_xor_sync(0xffffffffu, rs1, 2);
        l0 = l0 * corr0 + rs0;
        l1 = l1 * corr1 + rs1;

        // rescale O
#pragma unroll
        for (int nt = 0; nt < 8; nt++) {
            O[nt][0] *= corr0; O[nt][1] *= corr0;
            O[nt][2] *= corr1; O[nt][3] *= corr1;
        }

        // O += P @ V
#pragma unroll
        for (int nt = 0; nt < 8; nt++) {
            uint32_t bv[8];
            uint32_t va = vbase + ((nt * 8) << 1);
            ldm4t(bv,     va);
            ldm4t(bv + 4, va + ((32 * 72) << 1));
#pragma unroll
            for (int ks = 0; ks < 4; ks++)
                mmah(O[nt], P01[2 * ks], P23[2 * ks], P01[2 * ks + 1], P23[2 * ks + 1],
                     bv[2 * ks], bv[2 * ks + 1]);
        }
    }

    float inv0 = 1.0f / l0, inv1 = 1.0f / l1;
    float* cp = g_ctx + (size_t)bh * TKN * DK;
    int r0 = t0 + w * 16 + g;
#pragma unroll
    for (int nt = 0; nt < 8; nt++) {
        int col = nt * 8 + 2 * tg;
        *(float2*)(cp + (size_t)r0 * DK + col) =
            make_float2(O[nt][0] * inv0, O[nt][1] * inv0);
        *(float2*)(cp + (size_t)(r0 + 8) * DK + col) =
            make_float2(O[nt][2] * inv1, O[nt][3] * inv1);
    }
}

// ---------------------------------------------------------------------------
// Kernel 3: output projection via split-tf32 mma.sync (unchanged).
// ---------------------------------------------------------------------------
__global__ __launch_bounds__(256) void outproj_kernel(
    const float* __restrict__ Wo, const float* __restrict__ bo, float* __restrict__ out)
{
    __shared__ __align__(16) float Xs[128][36];
    __shared__ __align__(16) float Wos[128][36];
    __shared__ float sBias[128];

    int j0 = blockIdx.x * 128;
    int m0 = blockIdx.y * 128;

    int tid = threadIdx.x;
    int lane = tid & 31, w = tid >> 5;
    int wm = w & 3, wn = w >> 2;
    int g = lane >> 2, tg = lane & 3;

    if (tid < 128) sBias[tid] = bo[j0 + tid];

    const float* X = g_ctx;

    float acc[2][8][4];
#pragma unroll
    for (int mt = 0; mt < 2; mt++)
#pragma unroll
        for (int nt = 0; nt < 8; nt++)
#pragma unroll
            for (int q = 0; q < 4; q++) acc[mt][nt][q] = 0.0f;

    for (int d0 = 0; d0 < DM; d0 += 32) {
#pragma unroll
        for (int i = 0; i < 4; i++) {
            int idx = tid + i * 256;
            int r = idx >> 3, c4 = idx & 7;
            *(float4*)&Xs[r][c4 * 4] =
                *(const float4*)(X + (size_t)(m0 + r) * DM + d0 + c4 * 4);
            *(float4*)&Wos[r][c4 * 4] =
                *(const float4*)(Wo + (size_t)(j0 + r) * DM + d0 + c4 * 4);
        }
        __syncthreads();

#pragma unroll
        for (int kk = 0; kk < 32; kk += 8) {
            uint32_t ahi[2][4], alo[2][4];
#pragma unroll
            for (int mt = 0; mt < 2; mt++) {
                int rb = wm * 32 + mt * 16;
                tfsplit(Xs[rb + g][kk + tg],         ahi[mt][0], alo[mt][0]);
                tfsplit(Xs[rb + g + 8][kk + tg],     ahi[mt][1], alo[mt][1]);
                tfsplit(Xs[rb + g][kk + tg + 4],     ahi[mt][2], alo[mt][2]);
                tfsplit(Xs[rb + g + 8][kk + tg + 4], ahi[mt][3], alo[mt][3]);
            }
#pragma unroll
            for (int nh = 0; nh < 2; nh++) {
                uint32_t bhi[4][2], blo[4][2];
#pragma unroll
                for (int nt = 0; nt < 4; nt++) {
                    int nb = wn * 64 + (nh * 4 + nt) * 8;
                    tfsplit(Wos[nb + g][kk + tg],     bhi[nt][0], blo[nt][0]);
                    tfsplit(Wos[nb + g][kk + tg + 4], bhi[nt][1], blo[nt][1]);
                }
#pragma unroll
                for (int nt = 0; nt < 4; nt++)
#pragma unroll
                    for (int mt = 0; mt < 2; mt++)
                        mma8(acc[mt][nh * 4 + nt], ahi[mt][0], ahi[mt][1], ahi[mt][2], ahi[mt][3],
                             bhi[nt][0], bhi[nt][1]);
#pragma unroll
                for (int nt = 0; nt < 4; nt++)
#pragma unroll
                    for (int mt = 0; mt < 2; mt++)
                        mma8(acc[mt][nh * 4 + nt], alo[mt][0], alo[mt][1], alo[mt][2], alo[mt][3],
                             bhi[nt][0], bhi[nt][1]);
#pragma unroll
                for (int nt = 0; nt < 4; nt++)
#pragma unroll
                    for (int mt = 0; mt < 2; mt++)
                        mma8(acc[mt][nh * 4 + nt], ahi[mt][0], ahi[mt][1], ahi[mt][2], ahi[mt][3],
                             blo[nt][0], blo[nt][1]);
            }
        }
        __syncthreads();
    }

#pragma unroll
    for (int mt = 0; mt < 2; mt++) {
        int r0 = m0 + wm * 32 + mt * 16 + g;
#pragma unroll
        for (int nt = 0; nt < 8; nt++) {
            int cl = wn * 64 + nt * 8 + 2 * tg;
            float b0v = sBias[cl], b1v = sBias[cl + 1];
            *(float2*)(out + (size_t)r0 * DM + j0 + cl) =
                make_float2(acc[mt][nt][0] + b0v, acc[mt][nt][1] + b1v);
            *(float2*)(out + (size_t)(r0 + 8) * DM + j0 + cl) =
                make_float2(acc[mt][nt][2] + b0v, acc[mt][nt][3] + b1v);
        }
    }
}

// ---------------------------------------------------------------------------
extern "C" void kernel_launch(void* const* d_in, const int* in_sizes, int n_in,
                              void* d_out, int out_size)
{
    const float* Q  = (const float*)d_in[0];
    const float* K  = (const float*)d_in[1];
    const float* V  = (const float*)d_in[2];
    const float* Wq = (const float*)d_in[3];
    const float* bq = (const float*)d_in[4];
    const float* Wk = (const float*)d_in[5];
    const float* bk = (const float*)d_in[6];
    const float* Wv = (const float*)d_in[7];
    const float* bv = (const float*)d_in[8];
    const float* Wo = (const float*)d_in[9];
    const float* bo = (const float*)d_in[10];
    float* out = (float*)d_out;

    dim3 g1(TKN / 128, B_SZ * 8, 3);
    proj_kernel<<<g1, 256>>>(Q, K, V, Wq, bq, Wk, bk, Wv, bv);

    dim3 g2(TKN / 64, B_SZ * HEADS);
    flash_kernel<<<g2, 128>>>();

    dim3 g3(DM / 128, (B_SZ * TKN) / 128);
    outproj_kernel<<<g3, 256>>>(Wo, bo, out);
}

// round 5
// speedup vs baseline: 3.1205x; 1.5603x over previous
#include <cuda_runtime.h>
#include <cuda_fp16.h>
#include <cstdint>

#define B_SZ  2
#define HEADS 16
#define TKN   2048
#define DM    1024
#define DK    64

// ---- fp16 mma / ldmatrix / f16x2 helpers ----
__device__ __forceinline__ uint32_t cvta_s(const void* p) {
    return (uint32_t)__cvta_generic_to_shared(p);
}
__device__ __forceinline__ void ldm4(uint32_t* r, uint32_t a) {
    asm volatile("ldmatrix.sync.aligned.m8n8.x4.shared.b16 {%0,%1,%2,%3},[%4];"
        : "=r"(r[0]), "=r"(r[1]), "=r"(r[2]), "=r"(r[3]) : "r"(a));
}
__device__ __forceinline__ void ldm4t(uint32_t* r, uint32_t a) {
    asm volatile("ldmatrix.sync.aligned.m8n8.x4.trans.shared.b16 {%0,%1,%2,%3},[%4];"
        : "=r"(r[0]), "=r"(r[1]), "=r"(r[2]), "=r"(r[3]) : "r"(a));
}
__device__ __forceinline__ void mmah(float* d, uint32_t a0, uint32_t a1, uint32_t a2,
                                     uint32_t a3, uint32_t b0, uint32_t b1) {
    asm("mma.sync.aligned.m16n8k16.row.col.f32.f16.f16.f32 "
        "{%0,%1,%2,%3},{%4,%5,%6,%7},{%8,%9},{%0,%1,%2,%3};"
        : "+f"(d[0]), "+f"(d[1]), "+f"(d[2]), "+f"(d[3])
        : "r"(a0), "r"(a1), "r"(a2), "r"(a3), "r"(b0), "r"(b1));
}
__device__ __forceinline__ uint32_t cvt2h(float hi, float lo) {
    uint32_t d; asm("cvt.rn.f16x2.f32 %0, %1, %2;" : "=r"(d) : "f"(hi), "f"(lo)); return d;
}
__device__ __forceinline__ uint32_t ex2h2(uint32_t x) {
    uint32_t d; asm("ex2.approx.f16x2 %0, %1;" : "=r"(d) : "r"(x)); return d;
}
__device__ __forceinline__ float ex2f(float x) {
    float d; asm("ex2.approx.ftz.f32 %0, %1;" : "=f"(d) : "f"(x)); return d;
}
__device__ __forceinline__ uint32_t hadd2u(uint32_t a, uint32_t b) {
    uint32_t d; asm("add.rn.f16x2 %0, %1, %2;" : "=r"(d) : "r"(a), "r"(b)); return d;
}
__device__ __forceinline__ float h2sumf(uint32_t h) {
    __half2 v = *(__half2*)&h;
    return __low2float(v) + __high2float(v);
}
// f16 hi/lo split of an f32
__device__ __forceinline__ void hsplit(float x, __half& hi, __half& lo) {
    hi = __float2half_rn(x);
    lo = __float2half_rn(x - __half2float(hi));
}

// Scratch (allocation-free rule: __device__ globals)
__device__ __half g_Qh[B_SZ * HEADS * TKN * DK];   // pre-scaled by 1/8
__device__ __half g_Kh[B_SZ * HEADS * TKN * DK];
__device__ __half g_Vh[B_SZ * HEADS * TKN * DK];
__device__ float  g_ctx[B_SZ * HEADS * TKN * DK];

// ---------------------------------------------------------------------------
// Kernel 1: fused per-head Q/K/V projections via f16-split mma (3 passes).
// Block tile M=128(t) x N=128(2 heads), K-chunk 32. 8 warps = 4(M) x 2(N).
// X staged as f16 hi/lo [m][k]; W staged hi/lo [k][n] (B via ldmatrix.trans).
// ---------------------------------------------------------------------------
__global__ __launch_bounds__(256) void proj_kernel(
    const float* __restrict__ Q, const float* __restrict__ K, const float* __restrict__ V,
    const float* __restrict__ Wq, const float* __restrict__ bq,
    const float* __restrict__ Wk, const float* __restrict__ bk,
    const float* __restrict__ Wv, const float* __restrict__ bv)
{
    __shared__ __align__(16) __half XhS[128][40];
    __shared__ __align__(16) __half XlS[128][40];
    __shared__ __align__(16) __half WhS[32][136];
    __shared__ __align__(16) __half WlS[32][136];
    __shared__ float sBias[128];

    const float* X; const float* W; const float* bias; __half* out; float oscale;
    int z = blockIdx.z;
    if (z == 0)      { X = Q; W = Wq; bias = bq; out = g_Qh; oscale = 0.125f; }
    else if (z == 1) { X = K; W = Wk; bias = bk; out = g_Kh; oscale = 1.0f; }
    else             { X = V; W = Wv; bias = bv; out = g_Vh; oscale = 1.0f; }

    int y = blockIdx.y;
    int b = y >> 3, h0 = (y & 7) * 2;
    int t0 = blockIdx.x * 128;

    const float* Xb = X + ((size_t)b * TKN + t0) * DM;
    const float* W0 = W + (size_t)h0 * DM * DK;

    int tid = threadIdx.x;
    int lane = tid & 31, w = tid >> 5;
    int wm = w & 3, wn = w >> 2;
    int g = lane >> 2, tg = lane & 3;

    if (tid < 128) sBias[tid] = bias[h0 * DK + tid];

    float acc[2][8][4];
#pragma unroll
    for (int mt = 0; mt < 2; mt++)
#pragma unroll
        for (int nt = 0; nt < 8; nt++)
#pragma unroll
            for (int q = 0; q < 4; q++) acc[mt][nt][q] = 0.0f;

    // ldmatrix base addresses
    int arow = wm * 32 + ((lane >> 3) & 1) * 8 + (lane & 7);
    int acol = (lane >> 4) * 8;
    uint32_t abh = cvta_s(&XhS[arow][acol]);
    uint32_t abl = cvta_s(&XlS[arow][acol]);
    uint32_t wrow = (lane >> 3) * 8 + (lane & 7);   // k-row for trans B
    uint32_t wbh = cvta_s(WhS) + (wrow * 136) * 2;
    uint32_t wbl = cvta_s(WlS) + (wrow * 136) * 2;

    for (int d0 = 0; d0 < DM; d0 += 32) {
        // stage X tile (128 x 32) as hi/lo
#pragma unroll
        for (int i = 0; i < 4; i++) {
            int idx = tid + i * 256;
            int r = idx >> 3, c4 = idx & 7;
            float4 v = *(const float4*)(Xb + (size_t)r * DM + d0 + c4 * 4);
            __half h0v, l0v, h1v, l1v, h2v, l2v, h3v, l3v;
            hsplit(v.x, h0v, l0v); hsplit(v.y, h1v, l1v);
            hsplit(v.z, h2v, l2v); hsplit(v.w, h3v, l3v);
            *(__half2*)&XhS[r][c4 * 4]     = __halves2half2(h0v, h1v);
            *(__half2*)&XhS[r][c4 * 4 + 2] = __halves2half2(h2v, h3v);
            *(__half2*)&XlS[r][c4 * 4]     = __halves2half2(l0v, l1v);
            *(__half2*)&XlS[r][c4 * 4 + 2] = __halves2half2(l2v, l3v);
        }
        // stage W tile (32 k-rows x 128 cols, two heads) as hi/lo
#pragma unroll
        for (int i = 0; i < 4; i++) {
            int idx = tid + i * 256;
            int k = idx >> 5, c4 = idx & 31;
            const float* src = W0 + (c4 < 16 ? 0 : (size_t)DM * DK)
                               + (size_t)(d0 + k) * DK + (c4 & 15) * 4;
            float4 v = *(const float4*)src;
            __half h0v, l0v, h1v, l1v, h2v, l2v, h3v, l3v;
            hsplit(v.x, h0v, l0v); hsplit(v.y, h1v, l1v);
            hsplit(v.z, h2v, l2v); hsplit(v.w, h3v, l3v);
            *(__half2*)&WhS[k][c4 * 4]     = __halves2half2(h0v, h1v);
            *(__half2*)&WhS[k][c4 * 4 + 2] = __halves2half2(h2v, h3v);
            *(__half2*)&WlS[k][c4 * 4]     = __halves2half2(l0v, l1v);
            *(__half2*)&WlS[k][c4 * 4 + 2] = __halves2half2(l2v, l3v);
        }
        __syncthreads();

        uint32_t AH[2][2][4], AL[2][2][4];
#pragma unroll
        for (int mt = 0; mt < 2; mt++)
#pragma unroll
            for (int ks = 0; ks < 2; ks++) {
                ldm4(AH[mt][ks], abh + (mt * 16 * 40 + ks * 16) * 2);
                ldm4(AL[mt][ks], abl + (mt * 16 * 40 + ks * 16) * 2);
            }

#pragma unroll
        for (int nt = 0; nt < 8; nt++) {
            int nb = wn * 64 + nt * 8;
            uint32_t BH[4], BL[4];
            ldm4t(BH, wbh + nb * 2);
            ldm4t(BL, wbl + nb * 2);
            // pass 1: hi*hi
#pragma unroll
            for (int ks = 0; ks < 2; ks++)
#pragma unroll
                for (int mt = 0; mt < 2; mt++)
                    mmah(acc[mt][nt], AH[mt][ks][0], AH[mt][ks][1], AH[mt][ks][2], AH[mt][ks][3],
                         BH[2 * ks], BH[2 * ks + 1]);
            // pass 2: lo*hi
#pragma unroll
            for (int ks = 0; ks < 2; ks++)
#pragma unroll
                for (int mt = 0; mt < 2; mt++)
                    mmah(acc[mt][nt], AL[mt][ks][0], AL[mt][ks][1], AL[mt][ks][2], AL[mt][ks][3],
                         BH[2 * ks], BH[2 * ks + 1]);
            // pass 3: hi*lo
#pragma unroll
            for (int ks = 0; ks < 2; ks++)
#pragma unroll
                for (int mt = 0; mt < 2; mt++)
                    mmah(acc[mt][nt], AH[mt][ks][0], AH[mt][ks][1], AH[mt][ks][2], AH[mt][ks][3],
                         BL[2 * ks], BL[2 * ks + 1]);
        }
        __syncthreads();
    }

    __half* outh = out + ((size_t)(b * HEADS + h0 + wn) * TKN + t0) * DK;
#pragma unroll
    for (int mt = 0; mt < 2; mt++) {
        int r0 = wm * 32 + mt * 16 + g;
#pragma unroll
        for (int nt = 0; nt < 8; nt++) {
            int cl = nt * 8 + 2 * tg;
            float b0v = sBias[wn * 64 + cl], b1v = sBias[wn * 64 + cl + 1];
            *(__half2*)(outh + (size_t)r0 * DK + cl) =
                __floats2half2_rn((acc[mt][nt][0] + b0v) * oscale, (acc[mt][nt][1] + b1v) * oscale);
            *(__half2*)(outh + (size_t)(r0 + 8) * DK + cl) =
                __floats2half2_rn((acc[mt][nt][2] + b0v) * oscale, (acc[mt][nt][3] + b1v) * oscale);
        }
    }
}

// ---------------------------------------------------------------------------
// Kernel 2: flash attention, fp16 mma + f16x2 ex2 (unchanged from R4).
// ---------------------------------------------------------------------------
__global__ __launch_bounds__(128) void flash_kernel()
{
    __shared__ __half Qs[64][72];
    __shared__ __half Ks[64][72];
    __shared__ __half Vs[64][72];

    const float C = 1.4426950408889634f;

    int bh = blockIdx.y;
    int t0 = blockIdx.x * 64;
    const __half* Qp = g_Qh + (size_t)bh * TKN * DK;
    const __half* Kp = g_Kh + (size_t)bh * TKN * DK;
    const __half* Vp = g_Vh + (size_t)bh * TKN * DK;

    int tid = threadIdx.x;
    int lane = tid & 31, w = tid >> 5;
    int g = lane >> 2, tg = lane & 3;

#pragma unroll
    for (int i = 0; i < 4; i++) {
        int idx = i * 128 + tid;
        int r = idx >> 3, c = idx & 7;
        *(uint4*)&Qs[r][c * 8] = *(const uint4*)(Qp + (size_t)(t0 + r) * DK + c * 8);
    }
    __syncthreads();

    uint32_t Qa[4][4];
    {
        int qrow = w * 16 + ((lane >> 3) & 1) * 8 + (lane & 7);
        int qcol = (lane >> 4) * 8;
        uint32_t qbase = cvta_s(&Qs[qrow][qcol]);
#pragma unroll
        for (int ks = 0; ks < 4; ks++) ldm4(Qa[ks], qbase + ks * 32);
    }

    uint32_t kbase = cvta_s(Ks) + (((lane & 7) * 72 + (lane >> 3) * 8) << 1);
    uint32_t vbase = cvta_s(Vs) + ((((lane >> 3) * 8 + (lane & 7)) * 72) << 1);

    float m0 = -1e30f, m1 = -1e30f, l0 = 0.0f, l1 = 0.0f;
    float O[8][4];
#pragma unroll
    for (int nt = 0; nt < 8; nt++)
#pragma unroll
        for (int q = 0; q < 4; q++) O[nt][q] = 0.0f;

    for (int s0 = 0; s0 < TKN; s0 += 64) {
        __syncthreads();
#pragma unroll
        for (int i = 0; i < 4; i++) {
            int idx = i * 128 + tid;
            int r = idx >> 3, c = idx & 7;
            *(uint4*)&Ks[r][c * 8] = *(const uint4*)(Kp + (size_t)(s0 + r) * DK + c * 8);
            *(uint4*)&Vs[r][c * 8] = *(const uint4*)(Vp + (size_t)(s0 + r) * DK + c * 8);
        }
        __syncthreads();

        float S[8][4];
#pragma unroll
        for (int nt = 0; nt < 8; nt++) {
#pragma unroll
            for (int q = 0; q < 4; q++) S[nt][q] = 0.0f;
            uint32_t bk[8];
            uint32_t ka = kbase + ((nt * 8 * 72) << 1);
            ldm4(bk,     ka);
            ldm4(bk + 4, ka + 64);
#pragma unroll
            for (int ks = 0; ks < 4; ks++)
                mmah(S[nt], Qa[ks][0], Qa[ks][1], Qa[ks][2], Qa[ks][3],
                     bk[2 * ks], bk[2 * ks + 1]);
        }

        float mx0 = fmaxf(S[0][0], S[0][1]);
        float mx1 = fmaxf(S[0][2], S[0][3]);
#pragma unroll
        for (int nt = 1; nt < 8; nt++) {
            mx0 = fmaxf(mx0, fmaxf(S[nt][0], S[nt][1]));
            mx1 = fmaxf(mx1, fmaxf(S[nt][2], S[nt][3]));
        }
        mx0 = fmaxf(mx0, __shfl_xor_sync(0xffffffffu, mx0, 1));
        mx0 = fmaxf(mx0, __shfl_xor_sync(0xffffffffu, mx0, 2));
        mx1 = fmaxf(mx1, __shfl_xor_sync(0xffffffffu, mx1, 1));
        mx1 = fmaxf(mx1, __shfl_xor_sync(0xffffffffu, mx1, 2));

        float mn0 = fmaxf(m0, mx0), mn1 = fmaxf(m1, mx1);
        float corr0 = ex2f((m0 - mn0) * C);
        float corr1 = ex2f((m1 - mn1) * C);
        m0 = mn0; m1 = mn1;
        float mc0 = mn0 * C, mc1 = mn1 * C;

        uint32_t P01[8], P23[8];
#pragma unroll
        for (int nt = 0; nt < 8; nt++) {
            P01[nt] = ex2h2(cvt2h(fmaf(S[nt][1], C, -mc0), fmaf(S[nt][0], C, -mc0)));
            P23[nt] = ex2h2(cvt2h(fmaf(S[nt][3], C, -mc1), fmaf(S[nt][2], C, -mc1)));
        }

        uint32_t s01 = hadd2u(hadd2u(hadd2u(P01[0], P01[1]), hadd2u(P01[2], P01[3])),
                              hadd2u(hadd2u(P01[4], P01[5]), hadd2u(P01[6], P01[7])));
        uint32_t s23 = hadd2u(hadd2u(hadd2u(P23[0], P23[1]), hadd2u(P23[2], P23[3])),
                              hadd2u(hadd2u(P23[4], P23[5]), hadd2u(P23[6], P23[7])));
        float rs0 = h2sumf(s01), rs1 = h2sumf(s23);
        rs0 += __shfl_xor_sync(0xffffffffu, rs0, 1);
        rs0 += __shfl_xor_sync(0xffffffffu, rs0, 2);
        rs1 += __shfl_xor_sync(0xffffffffu, rs1, 1);
        rs1 += __shfl_xor_sync(0xffffffffu, rs1, 2);
        l0 = l0 * corr0 + rs0;
        l1 = l1 * corr1 + rs1;

#pragma unroll
        for (int nt = 0; nt < 8; nt++) {
            O[nt][0] *= corr0; O[nt][1] *= corr0;
            O[nt][2] *= corr1; O[nt][3] *= corr1;
        }

#pragma unroll
        for (int nt = 0; nt < 8; nt++) {
            uint32_t bv[8];
            uint32_t va = vbase + ((nt * 8) << 1);
            ldm4t(bv,     va);
            ldm4t(bv + 4, va + ((32 * 72) << 1));
#pragma unroll
            for (int ks = 0; ks < 4; ks++)
                mmah(O[nt], P01[2 * ks], P23[2 * ks], P01[2 * ks + 1], P23[2 * ks + 1],
                     bv[2 * ks], bv[2 * ks + 1]);
        }
    }

    float inv0 = 1.0f / l0, inv1 = 1.0f / l1;
    float* cp = g_ctx + (size_t)bh * TKN * DK;
    int r0 = t0 + w * 16 + g;
#pragma unroll
    for (int nt = 0; nt < 8; nt++) {
        int col = nt * 8 + 2 * tg;
        *(float2*)(cp + (size_t)r0 * DK + col) =
            make_float2(O[nt][0] * inv0, O[nt][1] * inv0);
        *(float2*)(cp + (size_t)(r0 + 8) * DK + col) =
            make_float2(O[nt][2] * inv1, O[nt][3] * inv1);
    }
}

// ---------------------------------------------------------------------------
// Kernel 3: output projection via f16-split mma (3 passes).
// A = ctx [m][d] (staged hi/lo), B = Wo rows [j][d] (non-trans ldmatrix,
// same pattern as flash's K operand).
// ---------------------------------------------------------------------------
__global__ __launch_bounds__(256) void outproj_kernel(
    const float* __restrict__ Wo, const float* __restrict__ bo, float* __restrict__ out)
{
    __shared__ __align__(16) __half XhS[128][40];
    __shared__ __align__(16) __half XlS[128][40];
    __shared__ __align__(16) __half WhS[128][40];
    __shared__ __align__(16) __half WlS[128][40];
    __shared__ float sBias[128];

    int j0 = blockIdx.x * 128;
    int m0 = blockIdx.y * 128;

    int tid = threadIdx.x;
    int lane = tid & 31, w = tid >> 5;
    int wm = w & 3, wn = w >> 2;
    int g = lane >> 2, tg = lane & 3;

    if (tid < 128) sBias[tid] = bo[j0 + tid];

    const float* X = g_ctx;

    float acc[2][8][4];
#pragma unroll
    for (int mt = 0; mt < 2; mt++)
#pragma unroll
        for (int nt = 0; nt < 8; nt++)
#pragma unroll
            for (int q = 0; q < 4; q++) acc[mt][nt][q] = 0.0f;

    int arow = wm * 32 + ((lane >> 3) & 1) * 8 + (lane & 7);
    int acol = (lane >> 4) * 8;
    uint32_t abh = cvta_s(&XhS[arow][acol]);
    uint32_t abl = cvta_s(&XlS[arow][acol]);
    uint32_t koff = ((lane & 7) * 40 + (lane >> 3) * 8) * 2;
    uint32_t kbh = cvta_s(WhS) + koff;
    uint32_t kbl = cvta_s(WlS) + koff;

    for (int d0 = 0; d0 < DM; d0 += 32) {
#pragma unroll
        for (int i = 0; i < 4; i++) {
            int idx = tid + i * 256;
            int r = idx >> 3, c4 = idx & 7;
            float4 v = *(const float4*)(X + (size_t)(m0 + r) * DM + d0 + c4 * 4);
            float4 u = *(const float4*)(Wo + (size_t)(j0 + r) * DM + d0 + c4 * 4);
            __half hh, ll;
            hsplit(v.x, hh, ll); XhS[r][c4*4]   = hh; XlS[r][c4*4]   = ll;
            hsplit(v.y, hh, ll); XhS[r][c4*4+1] = hh; XlS[r][c4*4+1] = ll;
            hsplit(v.z, hh, ll); XhS[r][c4*4+2] = hh; XlS[r][c4*4+2] = ll;
            hsplit(v.w, hh, ll); XhS[r][c4*4+3] = hh; XlS[r][c4*4+3] = ll;
            hsplit(u.x, hh, ll); WhS[r][c4*4]   = hh; WlS[r][c4*4]   = ll;
            hsplit(u.y, hh, ll); WhS[r][c4*4+1] = hh; WlS[r][c4*4+1] = ll;
            hsplit(u.z, hh, ll); WhS[r][c4*4+2] = hh; WlS[r][c4*4+2] = ll;
            hsplit(u.w, hh, ll); WhS[r][c4*4+3] = hh; WlS[r][c4*4+3] = ll;
        }
        __syncthreads();

        uint32_t AH[2][2][4], AL[2][2][4];
#pragma unroll
        for (int mt = 0; mt < 2; mt++)
#pragma unroll
            for (int ks = 0; ks < 2; ks++) {
                ldm4(AH[mt][ks], abh + (mt * 16 * 40 + ks * 16) * 2);
                ldm4(AL[mt][ks], abl + (mt * 16 * 40 + ks * 16) * 2);
            }

#pragma unroll
        for (int nt = 0; nt < 8; nt++) {
            int nb = wn * 64 + nt * 8;
            uint32_t BH[4], BL[4];
            ldm4(BH, kbh + (nb * 40) * 2);
            ldm4(BL, kbl + (nb * 40) * 2);
#pragma unroll
            for (int ks = 0; ks < 2; ks++)
#pragma unroll
                for (int mt = 0; mt < 2; mt++)
                    mmah(acc[mt][nt], AH[mt][ks][0], AH[mt][ks][1], AH[mt][ks][2], AH[mt][ks][3],
                         BH[2 * ks], BH[2 * ks + 1]);
#pragma unroll
            for (int ks = 0; ks < 2; ks++)
#pragma unroll
                for (int mt = 0; mt < 2; mt++)
                    mmah(acc[mt][nt], AL[mt][ks][0], AL[mt][ks][1], AL[mt][ks][2], AL[mt][ks][3],
                         BH[2 * ks], BH[2 * ks + 1]);
#pragma unroll
            for (int ks = 0; ks < 2; ks++)
#pragma unroll
                for (int mt = 0; mt < 2; mt++)
                    mmah(acc[mt][nt], AH[mt][ks][0], AH[mt][ks][1], AH[mt][ks][2], AH[mt][ks][3],
                         BL[2 * ks], BL[2 * ks + 1]);
        }
        __syncthreads();
    }

#pragma unroll
    for (int mt = 0; mt < 2; mt++) {
        int r0 = m0 + wm * 32 + mt * 16 + g;
#pragma unroll
        for (int nt = 0; nt < 8; nt++) {
            int cl = wn * 64 + nt * 8 + 2 * tg;
            float b0v = sBias[cl], b1v = sBias[cl + 1];
            *(float2*)(out + (size_t)r0 * DM + j0 + cl) =
                make_float2(acc[mt][nt][0] + b0v, acc[mt][nt][1] + b1v);
            *(float2*)(out + (size_t)(r0 + 8) * DM + j0 + cl) =
                make_float2(acc[mt][nt][2] + b0v, acc[mt][nt][3] + b1v);
        }
    }
}

// ---------------------------------------------------------------------------
extern "C" void kernel_launch(void* const* d_in, const int* in_sizes, int n_in,
                              void* d_out, int out_size)
{
    const float* Q  = (const float*)d_in[0];
    const float* K  = (const float*)d_in[1];
    const float* V  = (const float*)d_in[2];
    const float* Wq = (const float*)d_in[3];
    const float* bq = (const float*)d_in[4];
    const float* Wk = (const float*)d_in[5];
    const float* bk = (const float*)d_in[6];
    const float* Wv = (const float*)d_in[7];
    const float* bv = (const float*)d_in[8];
    const float* Wo = (const float*)d_in[9];
    const float* bo = (const float*)d_in[10];
    float* out = (float*)d_out;

    dim3 g1(TKN / 128, B_SZ * 8, 3);
    proj_kernel<<<g1, 256>>>(Q, K, V, Wq, bq, Wk, bk, Wv, bv);

    dim3 g2(TKN / 64, B_SZ * HEADS);
    flash_kernel<<<g2, 128>>>();

    dim3 g3(DM / 128, (B_SZ * TKN) / 128);
    outproj_kernel<<<g3, 256>>>(Wo, bo, out);
}

// round 6
// speedup vs baseline: 3.6461x; 1.1684x over previous
#include <cuda_runtime.h>
#include <cuda_fp16.h>
#include <cstdint>

#define B_SZ  2
#define HEADS 16
#define TKN   2048
#define DM    1024
#define DK    64

// ---- fp16 mma / ldmatrix / f16x2 helpers ----
__device__ __forceinline__ uint32_t cvta_s(const void* p) {
    return (uint32_t)__cvta_generic_to_shared(p);
}
__device__ __forceinline__ void ldm4(uint32_t* r, uint32_t a) {
    asm volatile("ldmatrix.sync.aligned.m8n8.x4.shared.b16 {%0,%1,%2,%3},[%4];"
        : "=r"(r[0]), "=r"(r[1]), "=r"(r[2]), "=r"(r[3]) : "r"(a));
}
__device__ __forceinline__ void ldm4t(uint32_t* r, uint32_t a) {
    asm volatile("ldmatrix.sync.aligned.m8n8.x4.trans.shared.b16 {%0,%1,%2,%3},[%4];"
        : "=r"(r[0]), "=r"(r[1]), "=r"(r[2]), "=r"(r[3]) : "r"(a));
}
__device__ __forceinline__ void mmah(float* d, uint32_t a0, uint32_t a1, uint32_t a2,
                                     uint32_t a3, uint32_t b0, uint32_t b1) {
    asm("mma.sync.aligned.m16n8k16.row.col.f32.f16.f16.f32 "
        "{%0,%1,%2,%3},{%4,%5,%6,%7},{%8,%9},{%0,%1,%2,%3};"
        : "+f"(d[0]), "+f"(d[1]), "+f"(d[2]), "+f"(d[3])
        : "r"(a0), "r"(a1), "r"(a2), "r"(a3), "r"(b0), "r"(b1));
}
__device__ __forceinline__ uint32_t cvt2h(float hi, float lo) {
    uint32_t d; asm("cvt.rn.f16x2.f32 %0, %1, %2;" : "=r"(d) : "f"(hi), "f"(lo)); return d;
}
__device__ __forceinline__ uint32_t ex2h2(uint32_t x) {
    uint32_t d; asm("ex2.approx.f16x2 %0, %1;" : "=r"(d) : "r"(x)); return d;
}
__device__ __forceinline__ float ex2f(float x) {
    float d; asm("ex2.approx.ftz.f32 %0, %1;" : "=f"(d) : "f"(x)); return d;
}
__device__ __forceinline__ uint32_t hadd2u(uint32_t a, uint32_t b) {
    uint32_t d; asm("add.rn.f16x2 %0, %1, %2;" : "=r"(d) : "r"(a), "r"(b)); return d;
}
__device__ __forceinline__ float h2sumf(uint32_t h) {
    __half2 v = *(__half2*)&h;
    return __low2float(v) + __high2float(v);
}
__device__ __forceinline__ void hsplit(float x, __half& hi, __half& lo) {
    hi = __float2half_rn(x);
    lo = __float2half_rn(x - __half2float(hi));
}
// cp.async 16B
__device__ __forceinline__ void cp16(uint32_t d, const void* s) {
    asm volatile("cp.async.ca.shared.global [%0], [%1], 16;" :: "r"(d), "l"(s));
}
__device__ __forceinline__ void cpcommit() {
    asm volatile("cp.async.commit_group;");
}
template <int N>
__device__ __forceinline__ void cpwait() {
    asm volatile("cp.async.wait_group %0;" :: "n"(N));
}

// ---- device-global scratch (no allocation) ----
__device__ __half g_Xh[3][B_SZ * TKN * DM];
__device__ __half g_Xl[3][B_SZ * TKN * DM];
__device__ __half g_Wh[3][HEADS * DM * DK];
__device__ __half g_Wl[3][HEADS * DM * DK];
__device__ __half g_Woh[DM * DM];
__device__ __half g_Wol[DM * DM];
__device__ __half g_Qh[B_SZ * HEADS * TKN * DK];   // pre-scaled by 1/8
__device__ __half g_Kh[B_SZ * HEADS * TKN * DK];
__device__ __half g_Vh[B_SZ * HEADS * TKN * DK];
__device__ __half g_ctxh[B_SZ * HEADS * TKN * DK];
__device__ __half g_ctxl[B_SZ * HEADS * TKN * DK];

// ---------------------------------------------------------------------------
// Kernel 0: split f32 tensors into f16 hi/lo pairs (bandwidth-bound).
// which: 0..2 -> X (Q,K,V); 3..5 -> W (q,k,v); 6 -> Wo
// ---------------------------------------------------------------------------
__global__ __launch_bounds__(256) void split_kernel(const float* __restrict__ src,
                                                    int which, int n4)
{
    __half *h, *l;
    if (which < 3)      { h = g_Xh[which];     l = g_Xl[which]; }
    else if (which < 6) { h = g_Wh[which - 3]; l = g_Wl[which - 3]; }
    else                { h = g_Woh;           l = g_Wol; }

    int i = blockIdx.x * blockDim.x + threadIdx.x;
    int stride = gridDim.x * blockDim.x;
    for (; i < n4; i += stride) {
        float4 v = ((const float4*)src)[i];
        __half h0, l0, h1, l1, h2, l2, h3, l3;
        hsplit(v.x, h0, l0); hsplit(v.y, h1, l1);
        hsplit(v.z, h2, l2); hsplit(v.w, h3, l3);
        ((__half2*)h)[2 * i]     = __halves2half2(h0, h1);
        ((__half2*)h)[2 * i + 1] = __halves2half2(h2, h3);
        ((__half2*)l)[2 * i]     = __halves2half2(l0, l1);
        ((__half2*)l)[2 * i + 1] = __halves2half2(l2, l3);
    }
}

// ---------------------------------------------------------------------------
// Kernel 1: QKV projections, f16-split mma, cp.async double-buffered.
// smem layout per stage (halfs): Xh[128][40] @0, Xl @5120, Wh[32][136] @10240,
// Wl @14592. Stage = 18944 halfs = 37888 B, x2 stages.
// ---------------------------------------------------------------------------
#define P_XL 5120
#define P_WH 10240
#define P_WL 14592
#define P_STAGE_B 37888

__global__ __launch_bounds__(256, 2) void proj_kernel(
    const float* __restrict__ bq, const float* __restrict__ bk, const float* __restrict__ bv)
{
    extern __shared__ __half sdyn[];
    __shared__ float sBias[128];

    int z = blockIdx.z;
    const float* bias = (z == 0) ? bq : (z == 1) ? bk : bv;
    __half* out = (z == 0) ? g_Qh : (z == 1) ? g_Kh : g_Vh;
    float oscale = (z == 0) ? 0.125f : 1.0f;

    int y = blockIdx.y;
    int b = y >> 3, h0 = (y & 7) * 2;
    int t0 = blockIdx.x * 128;

    const __half* Xhp = g_Xh[z] + ((size_t)b * TKN + t0) * DM;
    const __half* Xlp = g_Xl[z] + ((size_t)b * TKN + t0) * DM;
    const __half* Whp = g_Wh[z] + (size_t)h0 * DM * DK;
    const __half* Wlp = g_Wl[z] + (size_t)h0 * DM * DK;

    int tid = threadIdx.x;
    int lane = tid & 31, w = tid >> 5;
    int wm = w & 3, wn = w >> 2;
    int g = lane >> 2, tg = lane & 3;

    if (tid < 128) sBias[tid] = bias[h0 * DK + tid];

    uint32_t sb0 = cvta_s(sdyn);

    // staging chunk coords
    int xrow = tid >> 2, xseg = tid & 3;          // +64 rows for second chunk
    int wrow_c = tid >> 4, wcol_c = (tid & 15) * 8;
    size_t wso = (size_t)(wcol_c >= 64 ? DM * DK : 0) + (size_t)wrow_c * DK + (wcol_c & 63);

    float acc[2][8][4];
#pragma unroll
    for (int mt = 0; mt < 2; mt++)
#pragma unroll
        for (int nt = 0; nt < 8; nt++)
#pragma unroll
            for (int q = 0; q < 4; q++) acc[mt][nt][q] = 0.0f;

    // ldmatrix lane bases (offsets in halfs, stage-relative)
    int arow = wm * 32 + ((lane >> 3) & 1) * 8 + (lane & 7);
    int acol = (lane >> 4) * 8;
    uint32_t a_off  = (uint32_t)(arow * 40 + acol) * 2;
    uint32_t wrow_f = (uint32_t)((lane >> 3) * 8 + (lane & 7));
    uint32_t w_off  = (wrow_f * 136) * 2;

    auto stage = [&](int s, int d0) {
        uint32_t base = sb0 + s * P_STAGE_B;
#pragma unroll
        for (int i = 0; i < 2; i++) {
            int r = xrow + i * 64;
            size_t so = (size_t)r * DM + d0 + xseg * 8;
            uint32_t dof = (uint32_t)(r * 40 + xseg * 8) * 2;
            cp16(base + dof, Xhp + so);
            cp16(base + P_XL * 2 + dof, Xlp + so);
        }
#pragma unroll
        for (int i = 0; i < 2; i++) {
            int r = wrow_c + i * 16;
            size_t so = wso + (size_t)(d0 + i * 16) * DK;
            uint32_t dof = (uint32_t)(r * 136 + wcol_c) * 2;
            cp16(base + P_WH * 2 + dof, Whp + so);
            cp16(base + P_WL * 2 + dof, Wlp + so);
        }
        cpcommit();
    };

    stage(0, 0);

    const int nIter = DM / 32;
    for (int it = 0; it < nIter; it++) {
        if (it + 1 < nIter) { stage((it + 1) & 1, (it + 1) * 32); cpwait<1>(); }
        else                { cpwait<0>(); }
        __syncthreads();

        uint32_t base = sb0 + (it & 1) * P_STAGE_B;
        uint32_t abh = base + a_off;
        uint32_t abl = base + P_XL * 2 + a_off;
        uint32_t wbh = base + P_WH * 2 + w_off;
        uint32_t wbl = base + P_WL * 2 + w_off;

        uint32_t AH[2][2][4], AL[2][2][4];
#pragma unroll
        for (int mt = 0; mt < 2; mt++)
#pragma unroll
            for (int ks = 0; ks < 2; ks++) {
                ldm4(AH[mt][ks], abh + (mt * 16 * 40 + ks * 16) * 2);
                ldm4(AL[mt][ks], abl + (mt * 16 * 40 + ks * 16) * 2);
            }

#pragma unroll
        for (int nt = 0; nt < 8; nt++) {
            int nb = wn * 64 + nt * 8;
            uint32_t BH[4], BL[4];
            ldm4t(BH, wbh + nb * 2);
            ldm4t(BL, wbl + nb * 2);
#pragma unroll
            for (int ks = 0; ks < 2; ks++)
#pragma unroll
                for (int mt = 0; mt < 2; mt++)
                    mmah(acc[mt][nt], AH[mt][ks][0], AH[mt][ks][1], AH[mt][ks][2], AH[mt][ks][3],
                         BH[2 * ks], BH[2 * ks + 1]);
#pragma unroll
            for (int ks = 0; ks < 2; ks++)
#pragma unroll
                for (int mt = 0; mt < 2; mt++)
                    mmah(acc[mt][nt], AL[mt][ks][0], AL[mt][ks][1], AL[mt][ks][2], AL[mt][ks][3],
                         BH[2 * ks], BH[2 * ks + 1]);
#pragma unroll
            for (int ks = 0; ks < 2; ks++)
#pragma unroll
                for (int mt = 0; mt < 2; mt++)
                    mmah(acc[mt][nt], AH[mt][ks][0], AH[mt][ks][1], AH[mt][ks][2], AH[mt][ks][3],
                         BL[2 * ks], BL[2 * ks + 1]);
        }
        __syncthreads();
    }

    __half* outh = out + ((size_t)(b * HEADS + h0 + wn) * TKN + t0) * DK;
#pragma unroll
    for (int mt = 0; mt < 2; mt++) {
        int r0 = wm * 32 + mt * 16 + g;
#pragma unroll
        for (int nt = 0; nt < 8; nt++) {
            int cl = nt * 8 + 2 * tg;
            float b0v = sBias[wn * 64 + cl], b1v = sBias[wn * 64 + cl + 1];
            *(__half2*)(outh + (size_t)r0 * DK + cl) =
                __floats2half2_rn((acc[mt][nt][0] + b0v) * oscale, (acc[mt][nt][1] + b1v) * oscale);
            *(__half2*)(outh + (size_t)(r0 + 8) * DK + cl) =
                __floats2half2_rn((acc[mt][nt][2] + b0v) * oscale, (acc[mt][nt][3] + b1v) * oscale);
        }
    }
}

// ---------------------------------------------------------------------------
// Kernel 2: flash attention (unchanged math); epilogue writes ctx hi/lo f16.
// ---------------------------------------------------------------------------
__global__ __launch_bounds__(128) void flash_kernel()
{
    __shared__ __half Qs[64][72];
    __shared__ __half Ks[64][72];
    __shared__ __half Vs[64][72];

    const float C = 1.4426950408889634f;

    int bh = blockIdx.y;
    int t0 = blockIdx.x * 64;
    const __half* Qp = g_Qh + (size_t)bh * TKN * DK;
    const __half* Kp = g_Kh + (size_t)bh * TKN * DK;
    const __half* Vp = g_Vh + (size_t)bh * TKN * DK;

    int tid = threadIdx.x;
    int lane = tid & 31, w = tid >> 5;
    int g = lane >> 2, tg = lane & 3;

#pragma unroll
    for (int i = 0; i < 4; i++) {
        int idx = i * 128 + tid;
        int r = idx >> 3, c = idx & 7;
        *(uint4*)&Qs[r][c * 8] = *(const uint4*)(Qp + (size_t)(t0 + r) * DK + c * 8);
    }
    __syncthreads();

    uint32_t Qa[4][4];
    {
        int qrow = w * 16 + ((lane >> 3) & 1) * 8 + (lane & 7);
        int qcol = (lane >> 4) * 8;
        uint32_t qbase = cvta_s(&Qs[qrow][qcol]);
#pragma unroll
        for (int ks = 0; ks < 4; ks++) ldm4(Qa[ks], qbase + ks * 32);
    }

    uint32_t kbase = cvta_s(Ks) + (((lane & 7) * 72 + (lane >> 3) * 8) << 1);
    uint32_t vbase = cvta_s(Vs) + ((((lane >> 3) * 8 + (lane & 7)) * 72) << 1);

    float m0 = -1e30f, m1 = -1e30f, l0 = 0.0f, l1 = 0.0f;
    float O[8][4];
#pragma unroll
    for (int nt = 0; nt < 8; nt++)
#pragma unroll
        for (int q = 0; q < 4; q++) O[nt][q] = 0.0f;

    for (int s0 = 0; s0 < TKN; s0 += 64) {
        __syncthreads();
#pragma unroll
        for (int i = 0; i < 4; i++) {
            int idx = i * 128 + tid;
            int r = idx >> 3, c = idx & 7;
            *(uint4*)&Ks[r][c * 8] = *(const uint4*)(Kp + (size_t)(s0 + r) * DK + c * 8);
            *(uint4*)&Vs[r][c * 8] = *(const uint4*)(Vp + (size_t)(s0 + r) * DK + c * 8);
        }
        __syncthreads();

        float S[8][4];
#pragma unroll
        for (int nt = 0; nt < 8; nt++) {
#pragma unroll
            for (int q = 0; q < 4; q++) S[nt][q] = 0.0f;
            uint32_t bk[8];
            uint32_t ka = kbase + ((nt * 8 * 72) << 1);
            ldm4(bk,     ka);
            ldm4(bk + 4, ka + 64);
#pragma unroll
            for (int ks = 0; ks < 4; ks++)
                mmah(S[nt], Qa[ks][0], Qa[ks][1], Qa[ks][2], Qa[ks][3],
                     bk[2 * ks], bk[2 * ks + 1]);
        }

        float mx0 = fmaxf(S[0][0], S[0][1]);
        float mx1 = fmaxf(S[0][2], S[0][3]);
#pragma unroll
        for (int nt = 1; nt < 8; nt++) {
            mx0 = fmaxf(mx0, fmaxf(S[nt][0], S[nt][1]));
            mx1 = fmaxf(mx1, fmaxf(S[nt][2], S[nt][3]));
        }
        mx0 = fmaxf(mx0, __shfl_xor_sync(0xffffffffu, mx0, 1));
        mx0 = fmaxf(mx0, __shfl_xor_sync(0xffffffffu, mx0, 2));
        mx1 = fmaxf(mx1, __shfl_xor_sync(0xffffffffu, mx1, 1));
        mx1 = fmaxf(mx1, __shfl_xor_sync(0xffffffffu, mx1, 2));

        float mn0 = fmaxf(m0, mx0), mn1 = fmaxf(m1, mx1);
        float corr0 = ex2f((m0 - mn0) * C);
        float corr1 = ex2f((m1 - mn1) * C);
        m0 = mn0; m1 = mn1;
        float mc0 = mn0 * C, mc1 = mn1 * C;

        uint32_t P01[8], P23[8];
#pragma unroll
        for (int nt = 0; nt < 8; nt++) {
            P01[nt] = ex2h2(cvt2h(fmaf(S[nt][1], C, -mc0), fmaf(S[nt][0], C, -mc0)));
            P23[nt] = ex2h2(cvt2h(fmaf(S[nt][3], C, -mc1), fmaf(S[nt][2], C, -mc1)));
        }

        uint32_t s01 = hadd2u(hadd2u(hadd2u(P01[0], P01[1]), hadd2u(P01[2], P01[3])),
                              hadd2u(hadd2u(P01[4], P01[5]), hadd2u(P01[6], P01[7])));
        uint32_t s23 = hadd2u(hadd2u(hadd2u(P23[0], P23[1]), hadd2u(P23[2], P23[3])),
                              hadd2u(hadd2u(P23[4], P23[5]), hadd2u(P23[6], P23[7])));
        float rs0 = h2sumf(s01), rs1 = h2sumf(s23);
        rs0 += __shfl_xor_sync(0xffffffffu, rs0, 1);
        rs0 += __shfl_xor_sync(0xffffffffu, rs0, 2);
        rs1 += __shfl_xor_sync(0xffffffffu, rs1, 1);
        rs1 += __shfl_xor_sync(0xffffffffu, rs1, 2);
        l0 = l0 * corr0 + rs0;
        l1 = l1 * corr1 + rs1;

#pragma unroll
        for (int nt = 0; nt < 8; nt++) {
            O[nt][0] *= corr0; O[nt][1] *= corr0;
            O[nt][2] *= corr1; O[nt][3] *= corr1;
        }

#pragma unroll
        for (int nt = 0; nt < 8; nt++) {
            uint32_t bv[8];
            uint32_t va = vbase + ((nt * 8) << 1);
            ldm4t(bv,     va);
            ldm4t(bv + 4, va + ((32 * 72) << 1));
#pragma unroll
            for (int ks = 0; ks < 4; ks++)
                mmah(O[nt], P01[2 * ks], P23[2 * ks], P01[2 * ks + 1], P23[2 * ks + 1],
                     bv[2 * ks], bv[2 * ks + 1]);
        }
    }

    float inv0 = 1.0f / l0, inv1 = 1.0f / l1;
    size_t cb = (size_t)bh * TKN * DK;
    int r0 = t0 + w * 16 + g;
#pragma unroll
    for (int nt = 0; nt < 8; nt++) {
        int col = nt * 8 + 2 * tg;
        __half ah, al, bh2, bl2;
        hsplit(O[nt][0] * inv0, ah, al);
        hsplit(O[nt][1] * inv0, bh2, bl2);
        *(__half2*)(g_ctxh + cb + (size_t)r0 * DK + col) = __halves2half2(ah, bh2);
        *(__half2*)(g_ctxl + cb + (size_t)r0 * DK + col) = __halves2half2(al, bl2);
        hsplit(O[nt][2] * inv1, ah, al);
        hsplit(O[nt][3] * inv1, bh2, bl2);
        *(__half2*)(g_ctxh + cb + (size_t)(r0 + 8) * DK + col) = __halves2half2(ah, bh2);
        *(__half2*)(g_ctxl + cb + (size_t)(r0 + 8) * DK + col) = __halves2half2(al, bl2);
    }
}

// ---------------------------------------------------------------------------
// Kernel 3: output projection, f16-split mma, cp.async double-buffered.
// smem layout per stage (halfs): Ah[128][40] @0, Al @5120, Bh[128][40] @10240,
// Bl @15360. Stage = 20480 halfs = 40960 B, x2 stages.
// ---------------------------------------------------------------------------
#define O_AL 5120
#define O_BH 10240
#define O_BL 15360
#define O_STAGE_B 40960

__global__ __launch_bounds__(256, 2) void outproj_kernel(
    const float* __restrict__ bo, float* __restrict__ out)
{
    extern __shared__ __half sdyn[];
    __shared__ float sBias[128];

    int j0 = blockIdx.x * 128;
    int m0 = blockIdx.y * 128;

    int tid = threadIdx.x;
    int lane = tid & 31, w = tid >> 5;
    int wm = w & 3, wn = w >> 2;
    int g = lane >> 2, tg = lane & 3;

    if (tid < 128) sBias[tid] = bo[j0 + tid];

    uint32_t sb0 = cvta_s(sdyn);

    int xrow = tid >> 2, xseg = tid & 3;

    float acc[2][8][4];
#pragma unroll
    for (int mt = 0; mt < 2; mt++)
#pragma unroll
        for (int nt = 0; nt < 8; nt++)
#pragma unroll
            for (int q = 0; q < 4; q++) acc[mt][nt][q] = 0.0f;

    int arow = wm * 32 + ((lane >> 3) & 1) * 8 + (lane & 7);
    int acol = (lane >> 4) * 8;
    uint32_t a_off = (uint32_t)(arow * 40 + acol) * 2;
    uint32_t k_off = (uint32_t)((lane & 7) * 40 + (lane >> 3) * 8) * 2;

    auto stage = [&](int s, int d0) {
        uint32_t base = sb0 + s * O_STAGE_B;
#pragma unroll
        for (int i = 0; i < 2; i++) {
            int r = xrow + i * 64;
            uint32_t dof = (uint32_t)(r * 40 + xseg * 8) * 2;
            size_t soA = (size_t)(m0 + r) * DM + d0 + xseg * 8;
            size_t soB = (size_t)(j0 + r) * DM + d0 + xseg * 8;
            cp16(base + dof,             g_ctxh + soA);
            cp16(base + O_AL * 2 + dof,  g_ctxl + soA);
            cp16(base + O_BH * 2 + dof,  g_Woh + soB);
            cp16(base + O_BL * 2 + dof,  g_Wol + soB);
        }
        cpcommit();
    };

    stage(0, 0);

    const int nIter = DM / 32;
    for (int it = 0; it < nIter; it++) {
        if (it + 1 < nIter) { stage((it + 1) & 1, (it + 1) * 32); cpwait<1>(); }
        else                { cpwait<0>(); }
        __syncthreads();

        uint32_t base = sb0 + (it & 1) * O_STAGE_B;
        uint32_t abh = base + a_off;
        uint32_t abl = base + O_AL * 2 + a_off;
        uint32_t kbh = base + O_BH * 2 + k_off;
        uint32_t kbl = base + O_BL * 2 + k_off;

        uint32_t AH[2][2][4], AL[2][2][4];
#pragma unroll
        for (int mt = 0; mt < 2; mt++)
#pragma unroll
            for (int ks = 0; ks < 2; ks++) {
                ldm4(AH[mt][ks], abh + (mt * 16 * 40 + ks * 16) * 2);
                ldm4(AL[mt][ks], abl + (mt * 16 * 40 + ks * 16) * 2);
            }

#pragma unroll
        for (int nt = 0; nt < 8; nt++) {
            int nb = wn * 64 + nt * 8;
            uint32_t BH[4], BL[4];
            ldm4(BH, kbh + (nb * 40) * 2);
            ldm4(BL, kbl + (nb * 40) * 2);
#pragma unroll
            for (int ks = 0; ks < 2; ks++)
#pragma unroll
                for (int mt = 0; mt < 2; mt++)
                    mmah(acc[mt][nt], AH[mt][ks][0], AH[mt][ks][1], AH[mt][ks][2], AH[mt][ks][3],
                         BH[2 * ks], BH[2 * ks + 1]);
#pragma unroll
            for (int ks = 0; ks < 2; ks++)
#pragma unroll
                for (int mt = 0; mt < 2; mt++)
                    mmah(acc[mt][nt], AL[mt][ks][0], AL[mt][ks][1], AL[mt][ks][2], AL[mt][ks][3],
                         BH[2 * ks], BH[2 * ks + 1]);
#pragma unroll
            for (int ks = 0; ks < 2; ks++)
#pragma unroll
                for (int mt = 0; mt < 2; mt++)
                    mmah(acc[mt][nt], AH[mt][ks][0], AH[mt][ks][1], AH[mt][ks][2], AH[mt][ks][3],
                         BL[2 * ks], BL[2 * ks + 1]);
        }
        __syncthreads();
    }

#pragma unroll
    for (int mt = 0; mt < 2; mt++) {
        int r0 = m0 + wm * 32 + mt * 16 + g;
#pragma unroll
        for (int nt = 0; nt < 8; nt++) {
            int cl = wn * 64 + nt * 8 + 2 * tg;
            float b0v = sBias[cl], b1v = sBias[cl + 1];
            *(float2*)(out + (size_t)r0 * DM + j0 + cl) =
                make_float2(acc[mt][nt][0] + b0v, acc[mt][nt][1] + b1v);
            *(float2*)(out + (size_t)(r0 + 8) * DM + j0 + cl) =
                make_float2(acc[mt][nt][2] + b0v, acc[mt][nt][3] + b1v);
        }
    }
}

// ---------------------------------------------------------------------------
extern "C" void kernel_launch(void* const* d_in, const int* in_sizes, int n_in,
                              void* d_out, int out_size)
{
    const float* Q  = (const float*)d_in[0];
    const float* K  = (const float*)d_in[1];
    const float* V  = (const float*)d_in[2];
    const float* Wq = (const float*)d_in[3];
    const float* bq = (const float*)d_in[4];
    const float* Wk = (const float*)d_in[5];
    const float* bk = (const float*)d_in[6];
    const float* Wv = (const float*)d_in[7];
    const float* bv = (const float*)d_in[8];
    const float* Wo = (const float*)d_in[9];
    const float* bo = (const float*)d_in[10];
    float* out = (float*)d_out;

    cudaFuncSetAttribute(proj_kernel, cudaFuncAttributeMaxDynamicSharedMemorySize, 2 * P_STAGE_B);
    cudaFuncSetAttribute(outproj_kernel, cudaFuncAttributeMaxDynamicSharedMemorySize, 2 * O_STAGE_B);

    // prep: split inputs/weights into f16 hi/lo
    int nX4 = (B_SZ * TKN * DM) / 4;        // 1048576
    int nW4 = (HEADS * DM * DK) / 4;        // 262144
    split_kernel<<<512, 256>>>(Q, 0, nX4);
    split_kernel<<<512, 256>>>(K, 1, nX4);
    split_kernel<<<512, 256>>>(V, 2, nX4);
    split_kernel<<<256, 256>>>(Wq, 3, nW4);
    split_kernel<<<256, 256>>>(Wk, 4, nW4);
    split_kernel<<<256, 256>>>(Wv, 5, nW4);
    split_kernel<<<256, 256>>>(Wo, 6, (DM * DM) / 4);

    dim3 g1(TKN / 128, B_SZ * 8, 3);
    proj_kernel<<<g1, 256, 2 * P_STAGE_B>>>(bq, bk, bv);

    dim3 g2(TKN / 64, B_SZ * HEADS);
    flash_kernel<<<g2, 128>>>();

    dim3 g3(DM / 128, (B_SZ * TKN) / 128);
    outproj_kernel<<<g3, 256, 2 * O_STAGE_B>>>(bo, out);
}

// round 7
// speedup vs baseline: 6.4384x; 1.7658x over previous
#include <cuda_runtime.h>
#include <cuda_fp16.h>
#include <cstdint>

#define B_SZ  2
#define HEADS 16
#define TKN   2048
#define DM    1024
#define DK    64

// ---- fp16 mma / ldmatrix / f16x2 helpers ----
__device__ __forceinline__ uint32_t cvta_s(const void* p) {
    return (uint32_t)__cvta_generic_to_shared(p);
}
__device__ __forceinline__ void ldm4(uint32_t* r, uint32_t a) {
    asm volatile("ldmatrix.sync.aligned.m8n8.x4.shared.b16 {%0,%1,%2,%3},[%4];"
        : "=r"(r[0]), "=r"(r[1]), "=r"(r[2]), "=r"(r[3]) : "r"(a));
}
__device__ __forceinline__ void ldm4t(uint32_t* r, uint32_t a) {
    asm volatile("ldmatrix.sync.aligned.m8n8.x4.trans.shared.b16 {%0,%1,%2,%3},[%4];"
        : "=r"(r[0]), "=r"(r[1]), "=r"(r[2]), "=r"(r[3]) : "r"(a));
}
__device__ __forceinline__ void mmah(float* d, uint32_t a0, uint32_t a1, uint32_t a2,
                                     uint32_t a3, uint32_t b0, uint32_t b1) {
    asm("mma.sync.aligned.m16n8k16.row.col.f32.f16.f16.f32 "
        "{%0,%1,%2,%3},{%4,%5,%6,%7},{%8,%9},{%0,%1,%2,%3};"
        : "+f"(d[0]), "+f"(d[1]), "+f"(d[2]), "+f"(d[3])
        : "r"(a0), "r"(a1), "r"(a2), "r"(a3), "r"(b0), "r"(b1));
}
__device__ __forceinline__ uint32_t cvt2h(float hi, float lo) {
    uint32_t d; asm("cvt.rn.f16x2.f32 %0, %1, %2;" : "=r"(d) : "f"(hi), "f"(lo)); return d;
}
__device__ __forceinline__ uint32_t ex2h2(uint32_t x) {
    uint32_t d; asm("ex2.approx.f16x2 %0, %1;" : "=r"(d) : "r"(x)); return d;
}
__device__ __forceinline__ float ex2f(float x) {
    float d; asm("ex2.approx.ftz.f32 %0, %1;" : "=f"(d) : "f"(x)); return d;
}
__device__ __forceinline__ uint32_t hadd2u(uint32_t a, uint32_t b) {
    uint32_t d; asm("add.rn.f16x2 %0, %1, %2;" : "=r"(d) : "r"(a), "r"(b)); return d;
}
__device__ __forceinline__ float h2sumf(uint32_t h) {
    __half2 v = *(__half2*)&h;
    return __low2float(v) + __high2float(v);
}
__device__ __forceinline__ void hsplit(float x, __half& hi, __half& lo) {
    hi = __float2half_rn(x);
    lo = __float2half_rn(x - __half2float(hi));
}
// cp.async 16B
__device__ __forceinline__ void cp16(uint32_t d, const void* s) {
    asm volatile("cp.async.ca.shared.global [%0], [%1], 16;" :: "r"(d), "l"(s));
}
__device__ __forceinline__ void cpcommit() {
    asm volatile("cp.async.commit_group;");
}
template <int N>
__device__ __forceinline__ void cpwait() {
    asm volatile("cp.async.wait_group %0;" :: "n"(N));
}

// ---- device-global scratch (no allocation) ----
__device__ __half g_Xf[3][B_SZ * TKN * DM];      // f16(X) for Q,K,V inputs
__device__ __half g_Wf[3][HEADS * DM * DK];      // f16(W) for Wq,Wk,Wv
__device__ __half g_Wof[DM * DM];                // f16(Wo)
__device__ __half g_Qh[B_SZ * HEADS * TKN * DK]; // pre-scaled by 1/8
__device__ __half g_Kh[B_SZ * HEADS * TKN * DK];
__device__ __half g_Vh[B_SZ * HEADS * TKN * DK];
__device__ __half g_ctxh[B_SZ * HEADS * TKN * DK];
__device__ __half g_ctxl[B_SZ * HEADS * TKN * DK];

// ---------------------------------------------------------------------------
// Kernel 0: one fused f32 -> f16 convert pass for all 7 tensors.
// blockIdx.y selects the tensor.
// ---------------------------------------------------------------------------
__global__ __launch_bounds__(256) void split_kernel(
    const float* __restrict__ Q, const float* __restrict__ K, const float* __restrict__ V,
    const float* __restrict__ Wq, const float* __restrict__ Wk, const float* __restrict__ Wv,
    const float* __restrict__ Wo)
{
    int y = blockIdx.y;
    const float* src; __half* dst; int n4;
    switch (y) {
        case 0: src = Q;  dst = g_Xf[0]; n4 = (B_SZ * TKN * DM) / 4; break;
        case 1: src = K;  dst = g_Xf[1]; n4 = (B_SZ * TKN * DM) / 4; break;
        case 2: src = V;  dst = g_Xf[2]; n4 = (B_SZ * TKN * DM) / 4; break;
        case 3: src = Wq; dst = g_Wf[0]; n4 = (HEADS * DM * DK) / 4; break;
        case 4: src = Wk; dst = g_Wf[1]; n4 = (HEADS * DM * DK) / 4; break;
        case 5: src = Wv; dst = g_Wf[2]; n4 = (HEADS * DM * DK) / 4; break;
        default: src = Wo; dst = g_Wof;  n4 = (DM * DM) / 4; break;
    }
    int i = blockIdx.x * blockDim.x + threadIdx.x;
    int stride = gridDim.x * blockDim.x;
    for (; i < n4; i += stride) {
        float4 v = ((const float4*)src)[i];
        ((__half2*)dst)[2 * i]     = __floats2half2_rn(v.x, v.y);
        ((__half2*)dst)[2 * i + 1] = __floats2half2_rn(v.z, v.w);
    }
}

// ---------------------------------------------------------------------------
// Kernel 1: QKV projections, single-pass f16 mma, cp.async double-buffered.
// smem per stage (halfs): X[128][40] @0 (5120), W[32][136] @5120 (4352).
// Stage = 9472 halfs = 18944 B, x2 stages.
// ---------------------------------------------------------------------------
#define P_W   5120
#define P_STAGE_B 18944

__global__ __launch_bounds__(256, 2) void proj_kernel(
    const float* __restrict__ bq, const float* __restrict__ bk, const float* __restrict__ bv)
{
    extern __shared__ __half sdyn[];
    __shared__ float sBias[128];

    int z = blockIdx.z;
    const float* bias = (z == 0) ? bq : (z == 1) ? bk : bv;
    __half* out = (z == 0) ? g_Qh : (z == 1) ? g_Kh : g_Vh;
    float oscale = (z == 0) ? 0.125f : 1.0f;

    int y = blockIdx.y;
    int b = y >> 3, h0 = (y & 7) * 2;
    int t0 = blockIdx.x * 128;

    const __half* Xp = g_Xf[z] + ((size_t)b * TKN + t0) * DM;
    const __half* Wp = g_Wf[z] + (size_t)h0 * DM * DK;

    int tid = threadIdx.x;
    int lane = tid & 31, w = tid >> 5;
    int wm = w & 3, wn = w >> 2;
    int g = lane >> 2, tg = lane & 3;

    if (tid < 128) sBias[tid] = bias[h0 * DK + tid];

    uint32_t sb0 = cvta_s(sdyn);

    int xrow = tid >> 2, xseg = tid & 3;
    int wrow_c = tid >> 4, wcol_c = (tid & 15) * 8;
    size_t wso = (size_t)(wcol_c >= 64 ? DM * DK : 0) + (size_t)wrow_c * DK + (wcol_c & 63);

    float acc[2][8][4];
#pragma unroll
    for (int mt = 0; mt < 2; mt++)
#pragma unroll
        for (int nt = 0; nt < 8; nt++)
#pragma unroll
            for (int q = 0; q < 4; q++) acc[mt][nt][q] = 0.0f;

    int arow = wm * 32 + ((lane >> 3) & 1) * 8 + (lane & 7);
    int acol = (lane >> 4) * 8;
    uint32_t a_off = (uint32_t)(arow * 40 + acol) * 2;
    uint32_t w_off = ((uint32_t)((lane >> 3) * 8 + (lane & 7)) * 136) * 2;

    auto stage = [&](int s, int d0) {
        uint32_t base = sb0 + s * P_STAGE_B;
#pragma unroll
        for (int i = 0; i < 2; i++) {
            int r = xrow + i * 64;
            cp16(base + (uint32_t)(r * 40 + xseg * 8) * 2,
                 Xp + (size_t)r * DM + d0 + xseg * 8);
        }
#pragma unroll
        for (int i = 0; i < 2; i++) {
            int r = wrow_c + i * 16;
            cp16(base + P_W * 2 + (uint32_t)(r * 136 + wcol_c) * 2,
                 Wp + wso + (size_t)(d0 + i * 16) * DK);
        }
        cpcommit();
    };

    stage(0, 0);

    const int nIter = DM / 32;
    for (int it = 0; it < nIter; it++) {
        if (it > 0) __syncthreads();
        if (it + 1 < nIter) { stage((it + 1) & 1, (it + 1) * 32); cpwait<1>(); }
        else                { cpwait<0>(); }
        __syncthreads();

        uint32_t base = sb0 + (it & 1) * P_STAGE_B;
        uint32_t abh = base + a_off;
        uint32_t wbh = base + P_W * 2 + w_off;

        uint32_t AH[2][2][4];
#pragma unroll
        for (int mt = 0; mt < 2; mt++)
#pragma unroll
            for (int ks = 0; ks < 2; ks++)
                ldm4(AH[mt][ks], abh + (mt * 16 * 40 + ks * 16) * 2);

#pragma unroll
        for (int grp = 0; grp < 2; grp++) {
            uint32_t BH[4][4];
#pragma unroll
            for (int n4i = 0; n4i < 4; n4i++)
                ldm4t(BH[n4i], wbh + (wn * 64 + (grp * 4 + n4i) * 8) * 2);
#pragma unroll
            for (int ks = 0; ks < 2; ks++)
#pragma unroll
                for (int n4i = 0; n4i < 4; n4i++)
#pragma unroll
                    for (int mt = 0; mt < 2; mt++)
                        mmah(acc[mt][grp * 4 + n4i],
                             AH[mt][ks][0], AH[mt][ks][1], AH[mt][ks][2], AH[mt][ks][3],
                             BH[n4i][2 * ks], BH[n4i][2 * ks + 1]);
        }
    }

    __half* outh = out + ((size_t)(b * HEADS + h0 + wn) * TKN + t0) * DK;
#pragma unroll
    for (int mt = 0; mt < 2; mt++) {
        int r0 = wm * 32 + mt * 16 + g;
#pragma unroll
        for (int nt = 0; nt < 8; nt++) {
            int cl = nt * 8 + 2 * tg;
            float b0v = sBias[wn * 64 + cl], b1v = sBias[wn * 64 + cl + 1];
            *(__half2*)(outh + (size_t)r0 * DK + cl) =
                __floats2half2_rn((acc[mt][nt][0] + b0v) * oscale, (acc[mt][nt][1] + b1v) * oscale);
            *(__half2*)(outh + (size_t)(r0 + 8) * DK + cl) =
                __floats2half2_rn((acc[mt][nt][2] + b0v) * oscale, (acc[mt][nt][3] + b1v) * oscale);
        }
    }
}

// ---------------------------------------------------------------------------
// Kernel 2: flash attention; K/V double-buffered via cp.async.
// ---------------------------------------------------------------------------
__global__ __launch_bounds__(128) void flash_kernel()
{
    __shared__ __half Qs[64][72];
    __shared__ __half Ks[2][64][72];
    __shared__ __half Vs[2][64][72];

    const float C = 1.4426950408889634f;
    const uint32_t BUFB = 64 * 72 * 2;   // 9216 B per buffer

    int bh = blockIdx.y;
    int t0 = blockIdx.x * 64;
    const __half* Qp = g_Qh + (size_t)bh * TKN * DK;
    const __half* Kp = g_Kh + (size_t)bh * TKN * DK;
    const __half* Vp = g_Vh + (size_t)bh * TKN * DK;

    int tid = threadIdx.x;
    int lane = tid & 31, w = tid >> 5;
    int g = lane >> 2, tg = lane & 3;

    uint32_t ksb = cvta_s(Ks), vsb = cvta_s(Vs);

    auto stagekv = [&](int buf, int s0) {
#pragma unroll
        for (int i = 0; i < 4; i++) {
            int idx = i * 128 + tid;
            int r = idx >> 3, c = idx & 7;
            uint32_t dof = (uint32_t)(r * 72 + c * 8) * 2;
            cp16(ksb + buf * BUFB + dof, Kp + (size_t)(s0 + r) * DK + c * 8);
            cp16(vsb + buf * BUFB + dof, Vp + (size_t)(s0 + r) * DK + c * 8);
        }
        cpcommit();
    };

    stagekv(0, 0);

#pragma unroll
    for (int i = 0; i < 4; i++) {
        int idx = i * 128 + tid;
        int r = idx >> 3, c = idx & 7;
        *(uint4*)&Qs[r][c * 8] = *(const uint4*)(Qp + (size_t)(t0 + r) * DK + c * 8);
    }
    __syncthreads();

    uint32_t Qa[4][4];
    {
        int qrow = w * 16 + ((lane >> 3) & 1) * 8 + (lane & 7);
        int qcol = (lane >> 4) * 8;
        uint32_t qbase = cvta_s(&Qs[qrow][qcol]);
#pragma unroll
        for (int ks = 0; ks < 4; ks++) ldm4(Qa[ks], qbase + ks * 32);
    }

    uint32_t k_off = (((lane & 7) * 72 + (lane >> 3) * 8) << 1);
    uint32_t v_off = ((((lane >> 3) * 8 + (lane & 7)) * 72) << 1);

    float m0 = -1e30f, m1 = -1e30f, l0 = 0.0f, l1 = 0.0f;
    float O[8][4];
#pragma unroll
    for (int nt = 0; nt < 8; nt++)
#pragma unroll
        for (int q = 0; q < 4; q++) O[nt][q] = 0.0f;

    const int nCh = TKN / 64;
    for (int it = 0; it < nCh; it++) {
        if (it > 0) __syncthreads();
        if (it + 1 < nCh) { stagekv((it + 1) & 1, (it + 1) * 64); cpwait<1>(); }
        else              { cpwait<0>(); }
        __syncthreads();

        uint32_t kbase = ksb + (it & 1) * BUFB + k_off;
        uint32_t vbase = vsb + (it & 1) * BUFB + v_off;

        float S[8][4];
#pragma unroll
        for (int nt = 0; nt < 8; nt++) {
#pragma unroll
            for (int q = 0; q < 4; q++) S[nt][q] = 0.0f;
            uint32_t bk[8];
            uint32_t ka = kbase + ((nt * 8 * 72) << 1);
            ldm4(bk,     ka);
            ldm4(bk + 4, ka + 64);
#pragma unroll
            for (int ks = 0; ks < 4; ks++)
                mmah(S[nt], Qa[ks][0], Qa[ks][1], Qa[ks][2], Qa[ks][3],
                     bk[2 * ks], bk[2 * ks + 1]);
        }

        float mx0 = fmaxf(S[0][0], S[0][1]);
        float mx1 = fmaxf(S[0][2], S[0][3]);
#pragma unroll
        for (int nt = 1; nt < 8; nt++) {
            mx0 = fmaxf(mx0, fmaxf(S[nt][0], S[nt][1]));
            mx1 = fmaxf(mx1, fmaxf(S[nt][2], S[nt][3]));
        }
        mx0 = fmaxf(mx0, __shfl_xor_sync(0xffffffffu, mx0, 1));
        mx0 = fmaxf(mx0, __shfl_xor_sync(0xffffffffu, mx0, 2));
        mx1 = fmaxf(mx1, __shfl_xor_sync(0xffffffffu, mx1, 1));
        mx1 = fmaxf(mx1, __shfl_xor_sync(0xffffffffu, mx1, 2));

        float mn0 = fmaxf(m0, mx0), mn1 = fmaxf(m1, mx1);
        float corr0 = ex2f((m0 - mn0) * C);
        float corr1 = ex2f((m1 - mn1) * C);
        m0 = mn0; m1 = mn1;
        float mc0 = mn0 * C, mc1 = mn1 * C;

        uint32_t P01[8], P23[8];
#pragma unroll
        for (int nt = 0; nt < 8; nt++) {
            P01[nt] = ex2h2(cvt2h(fmaf(S[nt][1], C, -mc0), fmaf(S[nt][0], C, -mc0)));
            P23[nt] = ex2h2(cvt2h(fmaf(S[nt][3], C, -mc1), fmaf(S[nt][2], C, -mc1)));
        }

        uint32_t s01 = hadd2u(hadd2u(hadd2u(P01[0], P01[1]), hadd2u(P01[2], P01[3])),
                              hadd2u(hadd2u(P01[4], P01[5]), hadd2u(P01[6], P01[7])));
        uint32_t s23 = hadd2u(hadd2u(hadd2u(P23[0], P23[1]), hadd2u(P23[2], P23[3])),
                              hadd2u(hadd2u(P23[4], P23[5]), hadd2u(P23[6], P23[7])));
        float rs0 = h2sumf(s01), rs1 = h2sumf(s23);
        rs0 += __shfl_xor_sync(0xffffffffu, rs0, 1);
        rs0 += __shfl_xor_sync(0xffffffffu, rs0, 2);
        rs1 += __shfl_xor_sync(0xffffffffu, rs1, 1);
        rs1 += __shfl_xor_sync(0xffffffffu, rs1, 2);
        l0 = l0 * corr0 + rs0;
        l1 = l1 * corr1 + rs1;

#pragma unroll
        for (int nt = 0; nt < 8; nt++) {
            O[nt][0] *= corr0; O[nt][1] *= corr0;
            O[nt][2] *= corr1; O[nt][3] *= corr1;
        }

#pragma unroll
        for (int nt = 0; nt < 8; nt++) {
            uint32_t bv[8];
            uint32_t va = vbase + ((nt * 8) << 1);
            ldm4t(bv,     va);
            ldm4t(bv + 4, va + ((32 * 72) << 1));
#pragma unroll
            for (int ks = 0; ks < 4; ks++)
                mmah(O[nt], P01[2 * ks], P23[2 * ks], P01[2 * ks + 1], P23[2 * ks + 1],
                     bv[2 * ks], bv[2 * ks + 1]);
        }
    }

    float inv0 = 1.0f / l0, inv1 = 1.0f / l1;
    size_t cb = (size_t)bh * TKN * DK;
    int r0 = t0 + w * 16 + g;
#pragma unroll
    for (int nt = 0; nt < 8; nt++) {
        int col = nt * 8 + 2 * tg;
        __half ah, al, bh2, bl2;
        hsplit(O[nt][0] * inv0, ah, al);
        hsplit(O[nt][1] * inv0, bh2, bl2);
        *(__half2*)(g_ctxh + cb + (size_t)r0 * DK + col) = __halves2half2(ah, bh2);
        *(__half2*)(g_ctxl + cb + (size_t)r0 * DK + col) = __halves2half2(al, bl2);
        hsplit(O[nt][2] * inv1, ah, al);
        hsplit(O[nt][3] * inv1, bh2, bl2);
        *(__half2*)(g_ctxh + cb + (size_t)(r0 + 8) * DK + col) = __halves2half2(ah, bh2);
        *(__half2*)(g_ctxl + cb + (size_t)(r0 + 8) * DK + col) = __halves2half2(al, bl2);
    }
}

// ---------------------------------------------------------------------------
// Kernel 3: output projection, 2-pass (ctx_hi + ctx_lo) x Wo_hi.
// smem per stage (halfs): Ah[128][40] @0, Al @5120, Bh[128][40] @10240.
// Stage = 15360 halfs = 30720 B, x2 stages.
// ---------------------------------------------------------------------------
#define O_AL 5120
#define O_BH 10240
#define O_STAGE_B 30720

__global__ __launch_bounds__(256, 2) void outproj_kernel(
    const float* __restrict__ bo, float* __restrict__ out)
{
    extern __shared__ __half sdyn[];
    __shared__ float sBias[128];

    int j0 = blockIdx.x * 128;
    int m0 = blockIdx.y * 128;

    int tid = threadIdx.x;
    int lane = tid & 31, w = tid >> 5;
    int wm = w & 3, wn = w >> 2;
    int g = lane >> 2, tg = lane & 3;

    if (tid < 128) sBias[tid] = bo[j0 + tid];

    uint32_t sb0 = cvta_s(sdyn);
    int xrow = tid >> 2, xseg = tid & 3;

    float acc[2][8][4];
#pragma unroll
    for (int mt = 0; mt < 2; mt++)
#pragma unroll
        for (int nt = 0; nt < 8; nt++)
#pragma unroll
            for (int q = 0; q < 4; q++) acc[mt][nt][q] = 0.0f;

    int arow = wm * 32 + ((lane >> 3) & 1) * 8 + (lane & 7);
    int acol = (lane >> 4) * 8;
    uint32_t a_off = (uint32_t)(arow * 40 + acol) * 2;
    uint32_t k_off = (uint32_t)((lane & 7) * 40 + (lane >> 3) * 8) * 2;

    auto stage = [&](int s, int d0) {
        uint32_t base = sb0 + s * O_STAGE_B;
#pragma unroll
        for (int i = 0; i < 2; i++) {
            int r = xrow + i * 64;
            uint32_t dof = (uint32_t)(r * 40 + xseg * 8) * 2;
            size_t soA = (size_t)(m0 + r) * DM + d0 + xseg * 8;
            size_t soB = (size_t)(j0 + r) * DM + d0 + xseg * 8;
            cp16(base + dof,            g_ctxh + soA);
            cp16(base + O_AL * 2 + dof, g_ctxl + soA);
            cp16(base + O_BH * 2 + dof, g_Wof + soB);
        }
        cpcommit();
    };

    stage(0, 0);

    const int nIter = DM / 32;
    for (int it = 0; it < nIter; it++) {
        if (it > 0) __syncthreads();
        if (it + 1 < nIter) { stage((it + 1) & 1, (it + 1) * 32); cpwait<1>(); }
        else                { cpwait<0>(); }
        __syncthreads();

        uint32_t base = sb0 + (it & 1) * O_STAGE_B;
        uint32_t abh = base + a_off;
        uint32_t abl = base + O_AL * 2 + a_off;
        uint32_t kbh = base + O_BH * 2 + k_off;

        uint32_t AH[2][2][4], AL[2][2][4];
#pragma unroll
        for (int mt = 0; mt < 2; mt++)
#pragma unroll
            for (int ks = 0; ks < 2; ks++) {
                ldm4(AH[mt][ks], abh + (mt * 16 * 40 + ks * 16) * 2);
                ldm4(AL[mt][ks], abl + (mt * 16 * 40 + ks * 16) * 2);
            }

#pragma unroll
        for (int grp = 0; grp < 2; grp++) {
            uint32_t BH[4][4];
#pragma unroll
            for (int n4i = 0; n4i < 4; n4i++)
                ldm4(BH[n4i], kbh + ((wn * 64 + (grp * 4 + n4i) * 8) * 40) * 2);
#pragma unroll
            for (int ks = 0; ks < 2; ks++)
#pragma unroll
                for (int n4i = 0; n4i < 4; n4i++)
#pragma unroll
                    for (int mt = 0; mt < 2; mt++)
                        mmah(acc[mt][grp * 4 + n4i],
                             AH[mt][ks][0], AH[mt][ks][1], AH[mt][ks][2], AH[mt][ks][3],
                             BH[n4i][2 * ks], BH[n4i][2 * ks + 1]);
#pragma unroll
            for (int ks = 0; ks < 2; ks++)
#pragma unroll
                for (int n4i = 0; n4i < 4; n4i++)
#pragma unroll
                    for (int mt = 0; mt < 2; mt++)
                        mmah(acc[mt][grp * 4 + n4i],
                             AL[mt][ks][0], AL[mt][ks][1], AL[mt][ks][2], AL[mt][ks][3],
                             BH[n4i][2 * ks], BH[n4i][2 * ks + 1]);
        }
    }

#pragma unroll
    for (int mt = 0; mt < 2; mt++) {
        int r0 = m0 + wm * 32 + mt * 16 + g;
#pragma unroll
        for (int nt = 0; nt < 8; nt++) {
            int cl = wn * 64 + nt * 8 + 2 * tg;
            float b0v = sBias[cl], b1v = sBias[cl + 1];
            *(float2*)(out + (size_t)r0 * DM + j0 + cl) =
                make_float2(acc[mt][nt][0] + b0v, acc[mt][nt][1] + b1v);
            *(float2*)(out + (size_t)(r0 + 8) * DM + j0 + cl) =
                make_float2(acc[mt][nt][2] + b0v, acc[mt][nt][3] + b1v);
        }
    }
}

// ---------------------------------------------------------------------------
extern "C" void kernel_launch(void* const* d_in, const int* in_sizes, int n_in,
                              void* d_out, int out_size)
{
    const float* Q  = (const float*)d_in[0];
    const float* K  = (const float*)d_in[1];
    const float* V  = (const float*)d_in[2];
    const float* Wq = (const float*)d_in[3];
    const float* bq = (const float*)d_in[4];
    const float* Wk = (const float*)d_in[5];
    const float* bk = (const float*)d_in[6];
    const float* Wv = (const float*)d_in[7];
    const float* bv = (const float*)d_in[8];
    const float* Wo = (const float*)d_in[9];
    const float* bo = (const float*)d_in[10];
    float* out = (float*)d_out;

    cudaFuncSetAttribute(proj_kernel, cudaFuncAttributeMaxDynamicSharedMemorySize, 2 * P_STAGE_B);
    cudaFuncSetAttribute(outproj_kernel, cudaFuncAttributeMaxDynamicSharedMemorySize, 2 * O_STAGE_B);

    dim3 gs(128, 7);
    split_kernel<<<gs, 256>>>(Q, K, V, Wq, Wk, Wv, Wo);

    dim3 g1(TKN / 128, B_SZ * 8, 3);
    proj_kernel<<<g1, 256, 2 * P_STAGE_B>>>(bq, bk, bv);

    dim3 g2(TKN / 64, B_SZ * HEADS);
    flash_kernel<<<g2, 128>>>();

    dim3 g3(DM / 128, (B_SZ * TKN) / 128);
    outproj_kernel<<<g3, 256, 2 * O_STAGE_B>>>(bo, out);
}

// round 8
// speedup vs baseline: 6.7217x; 1.0440x over previous
#include <cuda_runtime.h>
#include <cuda_fp16.h>
#include <cstdint>

#define B_SZ  2
#define HEADS 16
#define TKN   2048
#define DM    1024
#define DK    64

// ---- fp16 mma / ldmatrix / f16x2 helpers ----
__device__ __forceinline__ uint32_t cvta_s(const void* p) {
    return (uint32_t)__cvta_generic_to_shared(p);
}
__device__ __forceinline__ void ldm4(uint32_t* r, uint32_t a) {
    asm volatile("ldmatrix.sync.aligned.m8n8.x4.shared.b16 {%0,%1,%2,%3},[%4];"
        : "=r"(r[0]), "=r"(r[1]), "=r"(r[2]), "=r"(r[3]) : "r"(a));
}
__device__ __forceinline__ void ldm4t(uint32_t* r, uint32_t a) {
    asm volatile("ldmatrix.sync.aligned.m8n8.x4.trans.shared.b16 {%0,%1,%2,%3},[%4];"
        : "=r"(r[0]), "=r"(r[1]), "=r"(r[2]), "=r"(r[3]) : "r"(a));
}
__device__ __forceinline__ void mmah(float* d, uint32_t a0, uint32_t a1, uint32_t a2,
                                     uint32_t a3, uint32_t b0, uint32_t b1) {
    asm("mma.sync.aligned.m16n8k16.row.col.f32.f16.f16.f32 "
        "{%0,%1,%2,%3},{%4,%5,%6,%7},{%8,%9},{%0,%1,%2,%3};"
        : "+f"(d[0]), "+f"(d[1]), "+f"(d[2]), "+f"(d[3])
        : "r"(a0), "r"(a1), "r"(a2), "r"(a3), "r"(b0), "r"(b1));
}
__device__ __forceinline__ uint32_t cvt2h(float hi, float lo) {
    uint32_t d; asm("cvt.rn.f16x2.f32 %0, %1, %2;" : "=r"(d) : "f"(hi), "f"(lo)); return d;
}
__device__ __forceinline__ uint32_t ex2h2(uint32_t x) {
    uint32_t d; asm("ex2.approx.f16x2 %0, %1;" : "=r"(d) : "r"(x)); return d;
}
__device__ __forceinline__ float ex2f(float x) {
    float d; asm("ex2.approx.ftz.f32 %0, %1;" : "=f"(d) : "f"(x)); return d;
}
__device__ __forceinline__ uint32_t hadd2u(uint32_t a, uint32_t b) {
    uint32_t d; asm("add.rn.f16x2 %0, %1, %2;" : "=r"(d) : "r"(a), "r"(b)); return d;
}
__device__ __forceinline__ float h2sumf(uint32_t h) {
    __half2 v = *(__half2*)&h;
    return __low2float(v) + __high2float(v);
}
// cp.async 16B
__device__ __forceinline__ void cp16(uint32_t d, const void* s) {
    asm volatile("cp.async.ca.shared.global [%0], [%1], 16;" :: "r"(d), "l"(s));
}
__device__ __forceinline__ void cpcommit() {
    asm volatile("cp.async.commit_group;");
}
template <int N>
__device__ __forceinline__ void cpwait() {
    asm volatile("cp.async.wait_group %0;" :: "n"(N));
}

// ---- device-global scratch (no allocation) ----
__device__ __half g_Xf[3][B_SZ * TKN * DM];      // f16(X) for Q,K,V inputs
__device__ __half g_Wf[3][HEADS * DM * DK];      // f16(W) for Wq,Wk,Wv
__device__ __half g_Wof[DM * DM];                // f16(Wo)
__device__ __half g_Qh[B_SZ * HEADS * TKN * DK]; // pre-scaled by 1/8
__device__ __half g_Kh[B_SZ * HEADS * TKN * DK];
__device__ __half g_Vh[B_SZ * HEADS * TKN * DK];
__device__ __half g_ctxh[B_SZ * HEADS * TKN * DK];

// ---------------------------------------------------------------------------
// Kernel 0: fused f32 -> f16 convert for all 7 tensors (blockIdx.y selects).
// ---------------------------------------------------------------------------
__global__ __launch_bounds__(256) void split_kernel(
    const float* __restrict__ Q, const float* __restrict__ K, const float* __restrict__ V,
    const float* __restrict__ Wq, const float* __restrict__ Wk, const float* __restrict__ Wv,
    const float* __restrict__ Wo)
{
    int y = blockIdx.y;
    const float* src; __half* dst; int n4;
    switch (y) {
        case 0: src = Q;  dst = g_Xf[0]; n4 = (B_SZ * TKN * DM) / 4; break;
        case 1: src = K;  dst = g_Xf[1]; n4 = (B_SZ * TKN * DM) / 4; break;
        case 2: src = V;  dst = g_Xf[2]; n4 = (B_SZ * TKN * DM) / 4; break;
        case 3: src = Wq; dst = g_Wf[0]; n4 = (HEADS * DM * DK) / 4; break;
        case 4: src = Wk; dst = g_Wf[1]; n4 = (HEADS * DM * DK) / 4; break;
        case 5: src = Wv; dst = g_Wf[2]; n4 = (HEADS * DM * DK) / 4; break;
        default: src = Wo; dst = g_Wof;  n4 = (DM * DM) / 4; break;
    }
    int i = blockIdx.x * blockDim.x + threadIdx.x;
    int stride = gridDim.x * blockDim.x;
    for (; i < n4; i += stride) {
        float4 v = ((const float4*)src)[i];
        ((__half2*)dst)[2 * i]     = __floats2half2_rn(v.x, v.y);
        ((__half2*)dst)[2 * i + 1] = __floats2half2_rn(v.z, v.w);
    }
}

// ---------------------------------------------------------------------------
// Kernel 1: QKV projections, single-pass f16 mma, 4-stage cp.async.
// smem per stage (halfs): X[128][40] @0 (5120), W[32][136] @5120 (4352).
// Stage = 9472 halfs = 18944 B, x4 stages.
// ---------------------------------------------------------------------------
#define P_W   5120
#define P_STAGE_B 18944

__global__ __launch_bounds__(256, 2) void proj_kernel(
    const float* __restrict__ bq, const float* __restrict__ bk, const float* __restrict__ bv)
{
    extern __shared__ __half sdyn[];
    __shared__ float sBias[128];

    int z = blockIdx.z;
    const float* bias = (z == 0) ? bq : (z == 1) ? bk : bv;
    __half* out = (z == 0) ? g_Qh : (z == 1) ? g_Kh : g_Vh;
    float oscale = (z == 0) ? 0.125f : 1.0f;

    int y = blockIdx.y;
    int b = y >> 3, h0 = (y & 7) * 2;
    int t0 = blockIdx.x * 128;

    const __half* Xp = g_Xf[z] + ((size_t)b * TKN + t0) * DM;
    const __half* Wp = g_Wf[z] + (size_t)h0 * DM * DK;

    int tid = threadIdx.x;
    int lane = tid & 31, w = tid >> 5;
    int wm = w & 3, wn = w >> 2;
    int g = lane >> 2, tg = lane & 3;

    if (tid < 128) sBias[tid] = bias[h0 * DK + tid];

    uint32_t sb0 = cvta_s(sdyn);

    int xrow = tid >> 2, xseg = tid & 3;
    int wrow_c = tid >> 4, wcol_c = (tid & 15) * 8;
    size_t wso = (size_t)(wcol_c >= 64 ? DM * DK : 0) + (size_t)wrow_c * DK + (wcol_c & 63);

    float acc[2][8][4];
#pragma unroll
    for (int mt = 0; mt < 2; mt++)
#pragma unroll
        for (int nt = 0; nt < 8; nt++)
#pragma unroll
            for (int q = 0; q < 4; q++) acc[mt][nt][q] = 0.0f;

    int arow = wm * 32 + ((lane >> 3) & 1) * 8 + (lane & 7);
    int acol = (lane >> 4) * 8;
    uint32_t a_off = (uint32_t)(arow * 40 + acol) * 2;
    uint32_t w_off = ((uint32_t)((lane >> 3) * 8 + (lane & 7)) * 136) * 2;

    auto stage = [&](int s, int d0) {
        uint32_t base = sb0 + s * P_STAGE_B;
#pragma unroll
        for (int i = 0; i < 2; i++) {
            int r = xrow + i * 64;
            cp16(base + (uint32_t)(r * 40 + xseg * 8) * 2,
                 Xp + (size_t)r * DM + d0 + xseg * 8);
        }
#pragma unroll
        for (int i = 0; i < 2; i++) {
            int r = wrow_c + i * 16;
            cp16(base + P_W * 2 + (uint32_t)(r * 136 + wcol_c) * 2,
                 Wp + wso + (size_t)(d0 + i * 16) * DK);
        }
        cpcommit();
    };

    stage(0, 0); stage(1, 32); stage(2, 64);

    const int nIter = DM / 32;
    for (int it = 0; it < nIter; it++) {
        if (it > 0) __syncthreads();
        if (it + 3 < nIter) { stage((it + 3) & 3, (it + 3) * 32); cpwait<3>(); }
        else if (it + 2 < nIter) cpwait<2>();
        else if (it + 1 < nIter) cpwait<1>();
        else cpwait<0>();
        __syncthreads();

        uint32_t base = sb0 + (it & 3) * P_STAGE_B;
        uint32_t abh = base + a_off;
        uint32_t wbh = base + P_W * 2 + w_off;

        uint32_t AH[2][2][4];
#pragma unroll
        for (int mt = 0; mt < 2; mt++)
#pragma unroll
            for (int ks = 0; ks < 2; ks++)
                ldm4(AH[mt][ks], abh + (mt * 16 * 40 + ks * 16) * 2);

#pragma unroll
        for (int grp = 0; grp < 2; grp++) {
            uint32_t BH[4][4];
#pragma unroll
            for (int n4i = 0; n4i < 4; n4i++)
                ldm4t(BH[n4i], wbh + (wn * 64 + (grp * 4 + n4i) * 8) * 2);
#pragma unroll
            for (int ks = 0; ks < 2; ks++)
#pragma unroll
                for (int n4i = 0; n4i < 4; n4i++)
#pragma unroll
                    for (int mt = 0; mt < 2; mt++)
                        mmah(acc[mt][grp * 4 + n4i],
                             AH[mt][ks][0], AH[mt][ks][1], AH[mt][ks][2], AH[mt][ks][3],
                             BH[n4i][2 * ks], BH[n4i][2 * ks + 1]);
        }
    }

    __half* outh = out + ((size_t)(b * HEADS + h0 + wn) * TKN + t0) * DK;
#pragma unroll
    for (int mt = 0; mt < 2; mt++) {
        int r0 = wm * 32 + mt * 16 + g;
#pragma unroll
        for (int nt = 0; nt < 8; nt++) {
            int cl = nt * 8 + 2 * tg;
            float b0v = sBias[wn * 64 + cl], b1v = sBias[wn * 64 + cl + 1];
            *(__half2*)(outh + (size_t)r0 * DK + cl) =
                __floats2half2_rn((acc[mt][nt][0] + b0v) * oscale, (acc[mt][nt][1] + b1v) * oscale);
            *(__half2*)(outh + (size_t)(r0 + 8) * DK + cl) =
                __floats2half2_rn((acc[mt][nt][2] + b0v) * oscale, (acc[mt][nt][3] + b1v) * oscale);
        }
    }
}

// ---------------------------------------------------------------------------
// Kernel 2: flash attention; 128 queries / 8 warps per CTA, K/V double-buffered.
// Warps 0-3 -> query rows [0,64), warps 4-7 -> [64,128) of the CTA tile.
// ---------------------------------------------------------------------------
__global__ __launch_bounds__(256) void flash_kernel()
{
    __shared__ __half Qs[128][72];
    __shared__ __half Ks[2][64][72];
    __shared__ __half Vs[2][64][72];

    const float C = 1.4426950408889634f;
    const uint32_t BUFB = 64 * 72 * 2;

    int bh = blockIdx.y;
    int t0 = blockIdx.x * 128;
    const __half* Qp = g_Qh + (size_t)bh * TKN * DK;
    const __half* Kp = g_Kh + (size_t)bh * TKN * DK;
    const __half* Vp = g_Vh + (size_t)bh * TKN * DK;

    int tid = threadIdx.x;
    int lane = tid & 31, w = tid >> 5;
    int wq = w >> 2, wi = w & 3;
    int g = lane >> 2, tg = lane & 3;

    uint32_t ksb = cvta_s(Ks), vsb = cvta_s(Vs);

    auto stagekv = [&](int buf, int s0) {
#pragma unroll
        for (int i = 0; i < 2; i++) {
            int idx = i * 256 + tid;
            int r = idx >> 3, c = idx & 7;
            uint32_t dof = (uint32_t)(r * 72 + c * 8) * 2;
            cp16(ksb + buf * BUFB + dof, Kp + (size_t)(s0 + r) * DK + c * 8);
            cp16(vsb + buf * BUFB + dof, Vp + (size_t)(s0 + r) * DK + c * 8);
        }
        cpcommit();
    };

    stagekv(0, 0);

#pragma unroll
    for (int i = 0; i < 4; i++) {
        int idx = i * 256 + tid;
        int r = idx >> 3, c = idx & 7;
        *(uint4*)&Qs[r][c * 8] = *(const uint4*)(Qp + (size_t)(t0 + r) * DK + c * 8);
    }
    __syncthreads();

    uint32_t Qa[4][4];
    {
        int qrow = wq * 64 + wi * 16 + ((lane >> 3) & 1) * 8 + (lane & 7);
        int qcol = (lane >> 4) * 8;
        uint32_t qbase = cvta_s(&Qs[qrow][qcol]);
#pragma unroll
        for (int ks = 0; ks < 4; ks++) ldm4(Qa[ks], qbase + ks * 32);
    }

    uint32_t k_off = (((lane & 7) * 72 + (lane >> 3) * 8) << 1);
    uint32_t v_off = ((((lane >> 3) * 8 + (lane & 7)) * 72) << 1);

    float m0 = -1e30f, m1 = -1e30f, l0 = 0.0f, l1 = 0.0f;
    float O[8][4];
#pragma unroll
    for (int nt = 0; nt < 8; nt++)
#pragma unroll
        for (int q = 0; q < 4; q++) O[nt][q] = 0.0f;

    const int nCh = TKN / 64;
    for (int it = 0; it < nCh; it++) {
        if (it > 0) __syncthreads();
        if (it + 1 < nCh) { stagekv((it + 1) & 1, (it + 1) * 64); cpwait<1>(); }
        else              { cpwait<0>(); }
        __syncthreads();

        uint32_t kbase = ksb + (it & 1) * BUFB + k_off;
        uint32_t vbase = vsb + (it & 1) * BUFB + v_off;

        float S[8][4];
#pragma unroll
        for (int nt = 0; nt < 8; nt++) {
#pragma unroll
            for (int q = 0; q < 4; q++) S[nt][q] = 0.0f;
            uint32_t bk[8];
            uint32_t ka = kbase + ((nt * 8 * 72) << 1);
            ldm4(bk,     ka);
            ldm4(bk + 4, ka + 64);
#pragma unroll
            for (int ks = 0; ks < 4; ks++)
                mmah(S[nt], Qa[ks][0], Qa[ks][1], Qa[ks][2], Qa[ks][3],
                     bk[2 * ks], bk[2 * ks + 1]);
        }

        float mx0 = fmaxf(S[0][0], S[0][1]);
        float mx1 = fmaxf(S[0][2], S[0][3]);
#pragma unroll
        for (int nt = 1; nt < 8; nt++) {
            mx0 = fmaxf(mx0, fmaxf(S[nt][0], S[nt][1]));
            mx1 = fmaxf(mx1, fmaxf(S[nt][2], S[nt][3]));
        }
        mx0 = fmaxf(mx0, __shfl_xor_sync(0xffffffffu, mx0, 1));
        mx0 = fmaxf(mx0, __shfl_xor_sync(0xffffffffu, mx0, 2));
        mx1 = fmaxf(mx1, __shfl_xor_sync(0xffffffffu, mx1, 1));
        mx1 = fmaxf(mx1, __shfl_xor_sync(0xffffffffu, mx1, 2));

        float mn0 = fmaxf(m0, mx0), mn1 = fmaxf(m1, mx1);
        float corr0 = ex2f((m0 - mn0) * C);
        float corr1 = ex2f((m1 - mn1) * C);
        m0 = mn0; m1 = mn1;
        float mc0 = mn0 * C, mc1 = mn1 * C;

        uint32_t P01[8], P23[8];
#pragma unroll
        for (int nt = 0; nt < 8; nt++) {
            P01[nt] = ex2h2(cvt2h(fmaf(S[nt][1], C, -mc0), fmaf(S[nt][0], C, -mc0)));
            P23[nt] = ex2h2(cvt2h(fmaf(S[nt][3], C, -mc1), fmaf(S[nt][2], C, -mc1)));
        }

        uint32_t s01 = hadd2u(hadd2u(hadd2u(P01[0], P01[1]), hadd2u(P01[2], P01[3])),
                              hadd2u(hadd2u(P01[4], P01[5]), hadd2u(P01[6], P01[7])));
        uint32_t s23 = hadd2u(hadd2u(hadd2u(P23[0], P23[1]), hadd2u(P23[2], P23[3])),
                              hadd2u(hadd2u(P23[4], P23[5]), hadd2u(P23[6], P23[7])));
        float rs0 = h2sumf(s01), rs1 = h2sumf(s23);
        rs0 += __shfl_xor_sync(0xffffffffu, rs0, 1);
        rs0 += __shfl_xor_sync(0xffffffffu, rs0, 2);
        rs1 += __shfl_xor_sync(0xffffffffu, rs1, 1);
        rs1 += __shfl_xor_sync(0xffffffffu, rs1, 2);
        l0 = l0 * corr0 + rs0;
        l1 = l1 * corr1 + rs1;

#pragma unroll
        for (int nt = 0; nt < 8; nt++) {
            O[nt][0] *= corr0; O[nt][1] *= corr0;
            O[nt][2] *= corr1; O[nt][3] *= corr1;
        }

#pragma unroll
        for (int nt = 0; nt < 8; nt++) {
            uint32_t bv[8];
            uint32_t va = vbase + ((nt * 8) << 1);
            ldm4t(bv,     va);
            ldm4t(bv + 4, va + ((32 * 72) << 1));
#pragma unroll
            for (int ks = 0; ks < 4; ks++)
                mmah(O[nt], P01[2 * ks], P23[2 * ks], P01[2 * ks + 1], P23[2 * ks + 1],
                     bv[2 * ks], bv[2 * ks + 1]);
        }
    }

    float inv0 = 1.0f / l0, inv1 = 1.0f / l1;
    size_t cb = (size_t)bh * TKN * DK;
    int r0 = t0 + wq * 64 + wi * 16 + g;
#pragma unroll
    for (int nt = 0; nt < 8; nt++) {
        int col = nt * 8 + 2 * tg;
        *(__half2*)(g_ctxh + cb + (size_t)r0 * DK + col) =
            __floats2half2_rn(O[nt][0] * inv0, O[nt][1] * inv0);
        *(__half2*)(g_ctxh + cb + (size_t)(r0 + 8) * DK + col) =
            __floats2half2_rn(O[nt][2] * inv1, O[nt][3] * inv1);
    }
}

// ---------------------------------------------------------------------------
// Kernel 3: output projection, single-pass ctx_hi x Wo_hi, 4-stage cp.async.
// smem per stage (halfs): A[128][40] @0, B[128][40] @5120. Stage = 20480 B.
// ---------------------------------------------------------------------------
#define O_BH 5120
#define O_STAGE_B 20480

__global__ __launch_bounds__(256, 2) void outproj_kernel(
    const float* __restrict__ bo, float* __restrict__ out)
{
    extern __shared__ __half sdyn[];
    __shared__ float sBias[128];

    int j0 = blockIdx.x * 128;
    int m0 = blockIdx.y * 128;

    int tid = threadIdx.x;
    int lane = tid & 31, w = tid >> 5;
    int wm = w & 3, wn = w >> 2;
    int g = lane >> 2, tg = lane & 3;

    if (tid < 128) sBias[tid] = bo[j0 + tid];

    uint32_t sb0 = cvta_s(sdyn);
    int xrow = tid >> 2, xseg = tid & 3;

    float acc[2][8][4];
#pragma unroll
    for (int mt = 0; mt < 2; mt++)
#pragma unroll
        for (int nt = 0; nt < 8; nt++)
#pragma unroll
            for (int q = 0; q < 4; q++) acc[mt][nt][q] = 0.0f;

    int arow = wm * 32 + ((lane >> 3) & 1) * 8 + (lane & 7);
    int acol = (lane >> 4) * 8;
    uint32_t a_off = (uint32_t)(arow * 40 + acol) * 2;
    uint32_t k_off = (uint32_t)((lane & 7) * 40 + (lane >> 3) * 8) * 2;

    auto stage = [&](int s, int d0) {
        uint32_t base = sb0 + s * O_STAGE_B;
#pragma unroll
        for (int i = 0; i < 2; i++) {
            int r = xrow + i * 64;
            uint32_t dof = (uint32_t)(r * 40 + xseg * 8) * 2;
            cp16(base + dof,            g_ctxh + (size_t)(m0 + r) * DM + d0 + xseg * 8);
            cp16(base + O_BH * 2 + dof, g_Wof  + (size_t)(j0 + r) * DM + d0 + xseg * 8);
        }
        cpcommit();
    };

    stage(0, 0); stage(1, 32); stage(2, 64);

    const int nIter = DM / 32;
    for (int it = 0; it < nIter; it++) {
        if (it > 0) __syncthreads();
        if (it + 3 < nIter) { stage((it + 3) & 3, (it + 3) * 32); cpwait<3>(); }
        else if (it + 2 < nIter) cpwait<2>();
        else if (it + 1 < nIter) cpwait<1>();
        else cpwait<0>();
        __syncthreads();

        uint32_t base = sb0 + (it & 3) * O_STAGE_B;
        uint32_t abh = base + a_off;
        uint32_t kbh = base + O_BH * 2 + k_off;

        uint32_t AH[2][2][4];
#pragma unroll
        for (int mt = 0; mt < 2; mt++)
#pragma unroll
            for (int ks = 0; ks < 2; ks++)
                ldm4(AH[mt][ks], abh + (mt * 16 * 40 + ks * 16) * 2);

#pragma unroll
        for (int grp = 0; grp < 2; grp++) {
            uint32_t BH[4][4];
#pragma unroll
            for (int n4i = 0; n4i < 4; n4i++)
                ldm4(BH[n4i], kbh + ((wn * 64 + (grp * 4 + n4i) * 8) * 40) * 2);
#pragma unroll
            for (int ks = 0; ks < 2; ks++)
#pragma unroll
                for (int n4i = 0; n4i < 4; n4i++)
#pragma unroll
                    for (int mt = 0; mt < 2; mt++)
                        mmah(acc[mt][grp * 4 + n4i],
                             AH[mt][ks][0], AH[mt][ks][1], AH[mt][ks][2], AH[mt][ks][3],
                             BH[n4i][2 * ks], BH[n4i][2 * ks + 1]);
        }
    }

#pragma unroll
    for (int mt = 0; mt < 2; mt++) {
        int r0 = m0 + wm * 32 + mt * 16 + g;
#pragma unroll
        for (int nt = 0; nt < 8; nt++) {
            int cl = wn * 64 + nt * 8 + 2 * tg;
            float b0v = sBias[cl], b1v = sBias[cl + 1];
            *(float2*)(out + (size_t)r0 * DM + j0 + cl) =
                make_float2(acc[mt][nt][0] + b0v, acc[mt][nt][1] + b1v);
            *(float2*)(out + (size_t)(r0 + 8) * DM + j0 + cl) =
                make_float2(acc[mt][nt][2] + b0v, acc[mt][nt][3] + b1v);
        }
    }
}

// ---------------------------------------------------------------------------
extern "C" void kernel_launch(void* const* d_in, const int* in_sizes, int n_in,
                              void* d_out, int out_size)
{
    const float* Q  = (const float*)d_in[0];
    const float* K  = (const float*)d_in[1];
    const float* V  = (const float*)d_in[2];
    const float* Wq = (const float*)d_in[3];
    const float* bq = (const float*)d_in[4];
    const float* Wk = (const float*)d_in[5];
    const float* bk = (const float*)d_in[6];
    const float* Wv = (const float*)d_in[7];
    const float* bv = (const float*)d_in[8];
    const float* Wo = (const float*)d_in[9];
    const float* bo = (const float*)d_in[10];
    float* out = (float*)d_out;

    cudaFuncSetAttribute(proj_kernel, cudaFuncAttributeMaxDynamicSharedMemorySize, 4 * P_STAGE_B);
    cudaFuncSetAttribute(outproj_kernel, cudaFuncAttributeMaxDynamicSharedMemorySize, 4 * O_STAGE_B);

    dim3 gs(128, 7);
    split_kernel<<<gs, 256>>>(Q, K, V, Wq, Wk, Wv, Wo);

    dim3 g1(TKN / 128, B_SZ * 8, 3);
    proj_kernel<<<g1, 256, 4 * P_STAGE_B>>>(bq, bk, bv);

    dim3 g2(TKN / 128, B_SZ * HEADS);
    flash_kernel<<<g2, 256>>>();

    dim3 g3(DM / 128, (B_SZ * TKN) / 128);
    outproj_kernel<<<g3, 256, 4 * O_STAGE_B>>>(bo, out);
}